// round 1
// baseline (speedup 1.0000x reference)
#include <cuda_runtime.h>
#include <cstdint>

#define KK 4
#define NN 2048
#define EE 4096
#define DD 128
#define NW 32               // N/64 words per edge-column bitset
#define BETA  0.6f
#define EPSG  0.01f
#define LAMS  0.05f
#define TC0C  0.3f
#define TCMAXC 0.7f

// ---------------- scratch (device globals; no allocation) ----------------
__device__ unsigned long long g_colbits[KK][EE][NW];   // 4 MB
__device__ float g_imp[KK][EE];
__device__ float g_eg[KK][EE];
__device__ float g_hval[KK][EE];
__device__ int   g_cnt[KK][EE];
__device__ float g_xhat[NN][DD];                       // 1 MB
__device__ float g_xnorm[NN];
__device__ float g_featn[KK];
__device__ float g_satt[KK];
__device__ float g_gates[KK];
__device__ unsigned long long g_adj[KK][NN][NN/64];    // 2 MB
__device__ float g_logits[KK][NN];

__device__ __forceinline__ float epoch_to_float(const int* p) {
    int ei = *p;
    return (ei >= 0 && ei < 1000000) ? (float)ei : __int_as_float(ei);
}

// ---------------- 0: zero accumulators + adjacency ----------------
__global__ void k_zero() {
    size_t idx = (size_t)blockIdx.x * blockDim.x + threadIdx.x;
    size_t stride = (size_t)gridDim.x * blockDim.x;
    unsigned long long* p = &g_adj[0][0][0];
    const size_t tot = (size_t)KK * NN * (NN/64);
    for (size_t i = idx; i < tot; i += stride) p[i] = 0ull;
    if (idx < KK) { g_featn[idx] = 0.f; g_satt[idx] = 0.f; }
}

// ---------------- 1: xhat / xnorm ----------------
__global__ void k_xhat(const float* __restrict__ X) {
    int n = blockIdx.x, t = threadIdx.x;   // 128 threads
    __shared__ float red[128];
    float v = X[(size_t)n * DD + t];
    red[t] = v * v; __syncthreads();
    for (int s = 64; s > 0; s >>= 1) { if (t < s) red[t] += red[t + s]; __syncthreads(); }
    float norm = sqrtf(red[0]);
    float inv = 1.f / fmaxf(norm, 1e-8f);
    g_xhat[n][t] = v * inv;
    if (t == 0) g_xnorm[n] = norm;
}

// ---------------- 2: edge stats + column bitsets (single H read) ----------------
__global__ void k_edge(const float* __restrict__ H) {
    int gid = blockIdx.x * 64 + threadIdx.x;       // one thread per (k,e)
    int k = gid / EE, e = gid % EE;
    const float* base = H + (size_t)k * NN * EE + e;
    int cnt = 0, i0 = 0, j0 = 0;
    for (int w = 0; w < NW; w++) {
        unsigned long long m = 0ull;
        #pragma unroll 8
        for (int b = 0; b < 64; b++) {
            float v = base[(size_t)(w * 64 + b) * EE];
            m |= ((unsigned long long)(v > 0.0f)) << b;
        }
        g_colbits[k][e][w] = m;
        int pc = __popcll(m);
        if (pc) {
            if (cnt == 0) {
                i0 = w * 64 + __ffsll((long long)m) - 1;
                if (pc >= 2) {
                    unsigned long long m2 = m & (m - 1);
                    j0 = w * 64 + __ffsll((long long)m2) - 1;
                }
            } else if (cnt == 1) {
                j0 = w * 64 + __ffsll((long long)m) - 1;
            }
            cnt += pc;
        }
    }
    g_cnt[k][e] = cnt;
    float imp = 0.f;
    if (e < 500) {
        if (cnt >= 2) {
            float dot = 0.f;
            const float* xi = g_xhat[i0];
            const float* xj = g_xhat[j0];
            #pragma unroll 8
            for (int d = 0; d < DD; d++) dot += xi[d] * xj[d];
            float A = base[(size_t)i0 * EE] * base[(size_t)j0 * EE];
            imp = A * dot;
        } else {
            imp = 0.1f;
        }
    }
    g_imp[k][e] = imp;
}

// ---------------- 3: component MLP + attention (tiled fp32) ----------------
__global__ __launch_bounds__(128) void k_gemm(
    const float* __restrict__ X,
    const float* __restrict__ w1, const float* __restrict__ b1,
    const float* __restrict__ w2, const float* __restrict__ b2,
    const float* __restrict__ aw1, const float* __restrict__ ab1,
    const float* __restrict__ aw2, const float* __restrict__ ab2)
{
    int k = blockIdx.y, nt = blockIdx.x, t = threadIdx.x;  // 128 threads
    __shared__ float Xs[DD][34];
    __shared__ float h1s[DD][34];
    __shared__ float a1s[64][34];
    __shared__ float red[128];

    // load 32 rows of X, transposed
    for (int idx = t; idx < 32 * DD; idx += 128) {
        int n = idx >> 7, d = idx & 127;
        Xs[d][n] = X[(size_t)(nt * 32 + n) * DD + d];
    }
    __syncthreads();

    // layer 1: h1 = relu(X @ w1 + b1), thread t owns output column t
    float acc[32];
    #pragma unroll
    for (int n = 0; n < 32; n++) acc[n] = 0.f;
    const float* W1 = w1 + (size_t)k * DD * DD;
    for (int d = 0; d < DD; d++) {
        float w = W1[d * DD + t];
        #pragma unroll
        for (int n = 0; n < 32; n += 2) {
            float2 x2 = *(const float2*)&Xs[d][n];
            acc[n]   += x2.x * w;
            acc[n+1] += x2.y * w;
        }
    }
    {
        float bb = b1[k * DD + t];
        #pragma unroll
        for (int n = 0; n < 32; n++) h1s[t][n] = fmaxf(acc[n] + bb, 0.f);
    }
    __syncthreads();

    // layer 2: Xk = h1 @ w2 + b2 ; store into Xs ; accumulate featn
    #pragma unroll
    for (int n = 0; n < 32; n++) acc[n] = 0.f;
    const float* W2 = w2 + (size_t)k * DD * DD;
    for (int d = 0; d < DD; d++) {
        float w = W2[d * DD + t];
        #pragma unroll
        for (int n = 0; n < 32; n += 2) {
            float2 x2 = *(const float2*)&h1s[d][n];
            acc[n]   += x2.x * w;
            acc[n+1] += x2.y * w;
        }
    }
    float fp = 0.f;
    {
        float b2v = b2[k * DD + t];
        #pragma unroll
        for (int n = 0; n < 32; n++) {
            float xk = acc[n] + b2v;
            fp += xk * xk;
            Xs[t][n] = xk;                 // safe: Xs last read before first sync
        }
    }
    __syncthreads();

    // attention layer 1 (64 hidden)
    if (t < 64) {
        float a3[32];
        #pragma unroll
        for (int n = 0; n < 32; n++) a3[n] = 0.f;
        const float* AW1 = aw1 + (size_t)k * DD * 64;
        for (int d = 0; d < DD; d++) {
            float w = AW1[d * 64 + t];
            #pragma unroll
            for (int n = 0; n < 32; n += 2) {
                float2 x2 = *(const float2*)&Xs[d][n];
                a3[n]   += x2.x * w;
                a3[n+1] += x2.y * w;
            }
        }
        float ab = ab1[k * 64 + t];
        #pragma unroll
        for (int n = 0; n < 32; n++) a1s[t][n] = fmaxf(a3[n] + ab, 0.f);
    }
    __syncthreads();

    // attention layer 2 + sigmoid
    float sattp = 0.f;
    if (t < 32) {
        int n = t;
        float s = ab2[k];
        const float* AW2 = aw2 + (size_t)k * 64;
        #pragma unroll 8
        for (int h = 0; h < 64; h++) s += a1s[h][n] * AW2[h];
        sattp = 1.f / (1.f + expf(-s));
    }

    // reductions
    red[t] = fp; __syncthreads();
    for (int s = 64; s > 0; s >>= 1) { if (t < s) red[t] += red[t + s]; __syncthreads(); }
    if (t == 0) atomicAdd(&g_featn[k], red[0]);
    __syncthreads();
    red[t] = sattp; __syncthreads();
    for (int s = 64; s > 0; s >>= 1) { if (t < s) red[t] += red[t + s]; __syncthreads(); }
    if (t == 0) atomicAdd(&g_satt[k], red[0]);
}

// ---------------- 4: component gates ----------------
__global__ void k_gates(const float* __restrict__ compW, const int* __restrict__ epochp,
                        float* __restrict__ out_gates)
{
    __shared__ float red[256];
    __shared__ float frob[KK];
    int t = threadIdx.x;
    for (int k = 0; k < KK; k++) {
        float s = 0.f;
        for (int i = t; i < DD * DD; i += 256) {
            float v = compW[(size_t)k * DD * DD + i];
            s += v * v;
        }
        red[t] = s; __syncthreads();
        for (int st = 128; st > 0; st >>= 1) { if (t < st) red[t] += red[t + st]; __syncthreads(); }
        if (t == 0) frob[k] = sqrtf(red[0]);
        __syncthreads();
    }
    if (t == 0) {
        float ep = epoch_to_float(epochp);
        float theta_c = TC0C + (1.f - expf(-LAMS * ep)) * (TCMAXC - TC0C);
        float imp[KK], pi[KK], g[KK];
        float m = -1e30f;
        for (int k = 0; k < KK; k++) {
            imp[k] = BETA * frob[k] * sqrtf(g_featn[k]) + (1.f - BETA) * (g_satt[k] / (float)NN);
            m = fmaxf(m, imp[k]);
        }
        float s = 0.f;
        for (int k = 0; k < KK; k++) { pi[k] = expf(imp[k] - m); s += pi[k]; }
        float gmax = -1.f; int am = 0;
        for (int k = 0; k < KK; k++) {
            pi[k] /= s;
            g[k] = fminf(fmaxf((pi[k] - theta_c) / EPSG + 0.5f, 0.f), 1.f);
            if (g[k] > gmax) { gmax = g[k]; am = k; }  // first-index tiebreak via strict >
        }
        g[am] = fmaxf(g[am], 1.f);
        for (int k = 0; k < KK; k++) { g_gates[k] = g[k]; out_gates[k] = g[k]; }
    }
}

// ---------------- 5: per-component edge softmax / eg ----------------
__global__ __launch_bounds__(512) void k_eg(const int* __restrict__ epochp,
                                            float* __restrict__ out_eg)
{
    const int k = blockIdx.x, t = threadIdx.x;   // 512 threads, 8 elems each
    __shared__ float pi[EE];
    __shared__ float red[512];
    __shared__ int redi[512];
    float lv[8];
    float vmax = -1e30f;
    #pragma unroll
    for (int r = 0; r < 8; r++) { lv[r] = g_imp[k][t + r * 512]; vmax = fmaxf(vmax, lv[r]); }
    red[t] = vmax; __syncthreads();
    for (int s = 256; s > 0; s >>= 1) { if (t < s) red[t] = fmaxf(red[t], red[t + s]); __syncthreads(); }
    const float M = red[0]; __syncthreads();

    float lsum = 0.f;
    #pragma unroll
    for (int r = 0; r < 8; r++) { float e_ = expf(lv[r] - M); pi[t + r * 512] = e_; lsum += e_; }
    red[t] = lsum; __syncthreads();
    for (int s = 256; s > 0; s >>= 1) { if (t < s) red[t] += red[t + s]; __syncthreads(); }
    const float S = red[0]; __syncthreads();
    const float invS = 1.f / S;

    float tsum = 0.f;
    #pragma unroll
    for (int r = 0; r < 8; r++) { float p = pi[t + r * 512] * invS; pi[t + r * 512] = p; tsum += p; }
    red[t] = tsum; __syncthreads();
    for (int s = 256; s > 0; s >>= 1) { if (t < s) red[t] += red[t + s]; __syncthreads(); }
    const float mean = red[0] / (float)EE; __syncthreads();

    float lvar = 0.f;
    #pragma unroll
    for (int r = 0; r < 8; r++) { float d = pi[t + r * 512] - mean; lvar += d * d; }
    red[t] = lvar; __syncthreads();
    for (int s = 256; s > 0; s >>= 1) { if (t < s) red[t] += red[t + s]; __syncthreads(); }
    const float stdv = sqrtf(red[0] / (float)(EE - 1)); __syncthreads();

    float ep = epoch_to_float(epochp);
    float theta_c = TC0C + (1.f - expf(-LAMS * ep)) * (TCMAXC - TC0C);
    float theta = fminf(theta_c, mean + stdv);

    float seg = 0.f, pmax = -1e30f; int pam = EE;
    #pragma unroll
    for (int r = 0; r < 8; r++) {
        int idx = t + r * 512;
        float p = pi[idx];
        float e_g = fminf(fmaxf((p - theta) / EPSG + 0.5f, 0.f), 1.f);
        lv[r] = e_g; seg += e_g;
        if (p > pmax) { pmax = p; pam = idx; }
    }
    red[t] = seg; __syncthreads();
    for (int s = 256; s > 0; s >>= 1) { if (t < s) red[t] += red[t + s]; __syncthreads(); }
    const float sumEg = red[0]; __syncthreads();

    red[t] = pmax; redi[t] = pam; __syncthreads();
    for (int s = 256; s > 0; s >>= 1) {
        if (t < s) {
            if (red[t + s] > red[t] || (red[t + s] == red[t] && redi[t + s] < redi[t])) {
                red[t] = red[t + s]; redi[t] = redi[t + s];
            }
        }
        __syncthreads();
    }
    const int am = redi[0];
    #pragma unroll
    for (int r = 0; r < 8; r++) {
        int idx = t + r * 512;
        float v = lv[r];
        if (sumEg < 1.f && idx == am) v = 1.f;
        g_eg[k][idx] = v;
        out_eg[(size_t)k * EE + idx] = v;
    }
}

// ---------------- 6: effective per-edge Hp value ----------------
__global__ void k_hval() {
    int gid = blockIdx.x * blockDim.x + threadIdx.x;
    int k = gid / EE, e = gid % EE;
    float g = g_gates[k];
    g_hval[k][e] = g * (g > 0.5f ? g_eg[k][e] : 1.f);
}

// ---------------- 7: write Hp from bitsets (write-only 134 MB) ----------------
__global__ __launch_bounds__(256) void k_hp(float* __restrict__ out) {
    int k = blockIdx.z, nt = blockIdx.y, et = blockIdx.x;
    int t = threadIdx.x;  // 256
    __shared__ unsigned long long bw[128];
    __shared__ float hv[128];
    if (t < 128) {
        hv[t] = g_hval[k][et * 128 + t];
        bw[t] = g_colbits[k][et * 128 + t][nt];
    }
    __syncthreads();
    #pragma unroll
    for (int r = 0; r < 8; r++) {
        int idx = t + r * 256;
        int nl = idx >> 5, q = idx & 31, el = q * 4;
        float4 v;
        v.x = ((bw[el + 0] >> nl) & 1ull) ? hv[el + 0] : 0.f;
        v.y = ((bw[el + 1] >> nl) & 1ull) ? hv[el + 1] : 0.f;
        v.z = ((bw[el + 2] >> nl) & 1ull) ? hv[el + 2] : 0.f;
        v.w = ((bw[el + 3] >> nl) & 1ull) ? hv[el + 3] : 0.f;
        *(float4*)&out[((size_t)k * NN + (size_t)nt * 64 + nl) * EE + et * 128 + el] = v;
    }
}

// ---------------- 8: sparse adjacency build (warp per edge) ----------------
__global__ __launch_bounds__(256) void k_adj() {
    int wId = (blockIdx.x * blockDim.x + threadIdx.x) >> 5;
    int lane = threadIdx.x & 31;
    int wl = threadIdx.x >> 5;
    int k = wId / EE, e = wId % EE;
    __shared__ unsigned short list[8][1024];
    __shared__ int scnt[8];
    if (g_hval[k][e] <= 0.f) return;       // warp-uniform
    if (g_cnt[k][e] < 2) return;
    if (lane == 0) scnt[wl] = 0;
    __syncwarp();
    unsigned long long m = g_colbits[k][e][lane];  // 32 words <-> 32 lanes
    while (m) {
        int b = __ffsll((long long)m) - 1;
        m &= m - 1;
        int pos = atomicAdd(&scnt[wl], 1);
        if (pos < 1024) list[wl][pos] = (unsigned short)(lane * 64 + b);
    }
    __syncwarp();
    int cN = scnt[wl];
    if (cN > 1024) cN = 1024;
    for (int p = lane; p < cN * cN; p += 32) {
        int u = list[wl][p / cN];
        int v = list[wl][p % cN];
        if (u != v)
            atomicOr(&g_adj[k][u][v >> 6], 1ull << (v & 63));
    }
}

// ---------------- 9: neighbor sum -> logits ----------------
__global__ __launch_bounds__(128) void k_nsum() {
    int u = blockIdx.x, k = blockIdx.y, t = threadIdx.x;  // 128 threads
    __shared__ unsigned short list[NN];
    __shared__ int s_deg;
    __shared__ float red[128];
    if (t < 32) {
        unsigned long long m = g_adj[k][u][t];
        int c = __popcll(m);
        int off = c;
        #pragma unroll
        for (int d = 1; d < 32; d <<= 1) {
            int x = __shfl_up_sync(0xffffffffu, off, d);
            if (t >= d) off += x;
        }
        off -= c;                     // exclusive prefix => deterministic ordering
        int pos = off;
        while (m) {
            int b = __ffsll((long long)m) - 1;
            m &= m - 1;
            list[pos++] = (unsigned short)(t * 64 + b);
        }
        if (t == 31) s_deg = off + c;
    }
    __syncthreads();
    int deg = s_deg;
    float acc = 0.f;
    for (int i = 0; i < deg; i++) acc += g_xhat[list[i]][t];
    red[t] = g_xhat[u][t] * acc;
    __syncthreads();
    for (int s = 64; s > 0; s >>= 1) { if (t < s) red[t] += red[t + s]; __syncthreads(); }
    if (t == 0) {
        float avg = (deg > 0) ? red[0] / (float)deg : 0.f;
        g_logits[k][u] = avg * g_xnorm[u];
    }
}

// ---------------- 10: npi softmax over nodes ----------------
__global__ __launch_bounds__(512) void k_npi(float* __restrict__ out_npi) {
    int k = blockIdx.x, t = threadIdx.x;  // 512 threads, 4 elems each
    __shared__ float red[512];
    float lv[4];
    float m = -1e30f;
    #pragma unroll
    for (int r = 0; r < 4; r++) { lv[r] = g_logits[k][t + r * 512]; m = fmaxf(m, lv[r]); }
    red[t] = m; __syncthreads();
    for (int s = 256; s > 0; s >>= 1) { if (t < s) red[t] = fmaxf(red[t], red[t + s]); __syncthreads(); }
    const float M = red[0]; __syncthreads();
    float ls = 0.f;
    #pragma unroll
    for (int r = 0; r < 4; r++) { lv[r] = expf(lv[r] - M); ls += lv[r]; }
    red[t] = ls; __syncthreads();
    for (int s = 256; s > 0; s >>= 1) { if (t < s) red[t] += red[t + s]; __syncthreads(); }
    const float invS = 1.f / red[0];
    #pragma unroll
    for (int r = 0; r < 4; r++)
        out_npi[(size_t)k * NN + t + r * 512] = lv[r] * invS;
}

// ---------------- launch ----------------
extern "C" void kernel_launch(void* const* d_in, const int* in_sizes, int n_in,
                              void* d_out, int out_size) {
    const float* H     = (const float*)d_in[0];
    const float* X     = (const float*)d_in[1];
    const int*   epoch = (const int*)  d_in[2];
    const float* w1    = (const float*)d_in[3];
    const float* b1    = (const float*)d_in[4];
    const float* w2    = (const float*)d_in[5];
    const float* b2    = (const float*)d_in[6];
    const float* compW = (const float*)d_in[7];
    const float* aw1   = (const float*)d_in[8];
    const float* ab1   = (const float*)d_in[9];
    const float* aw2   = (const float*)d_in[10];
    const float* ab2   = (const float*)d_in[11];
    float* out = (float*)d_out;

    const size_t OFF_G = (size_t)KK * NN * EE;
    const size_t OFF_E = OFF_G + KK;
    const size_t OFF_P = OFF_E + (size_t)KK * EE;

    k_zero<<<512, 256>>>();
    k_xhat<<<NN, 128>>>(X);
    k_edge<<<KK * EE / 64, 64>>>(H);
    k_gemm<<<dim3(NN / 32, KK), 128>>>(X, w1, b1, w2, b2, aw1, ab1, aw2, ab2);
    k_gates<<<1, 256>>>(compW, epoch, out + OFF_G);
    k_eg<<<KK, 512>>>(epoch, out + OFF_E);
    k_hval<<<KK * EE / 256, 256>>>();
    k_hp<<<dim3(EE / 128, NN / 64, KK), 256>>>(out);
    k_adj<<<KK * EE / 8, 256>>>();
    k_nsum<<<dim3(NN, KK), 128>>>();
    k_npi<<<KK, 512>>>(out + OFF_P);
}

// round 2
// speedup vs baseline: 2.1576x; 2.1576x over previous
#include <cuda_runtime.h>
#include <cstdint>

#define KK 4
#define NN 2048
#define EE 4096
#define DD 128
#define NW 32               // N/64 words per edge-column bitset
#define BETA  0.6f
#define EPSG  0.01f
#define LAMS  0.05f
#define TC0C  0.3f
#define TCMAXC 0.7f

typedef unsigned long long ull;

// ---------------- scratch (device globals; no allocation) ----------------
__device__ ull   g_colbits[KK][EE][NW];   // 4 MB
__device__ float g_imp[KK][EE];
__device__ float g_eg[KK][EE];
__device__ float g_hval[KK][EE];
__device__ int   g_cnt[KK][EE];
__device__ int2  g_ij[KK][EE];
__device__ float g_xhat[NN][DD];          // 1 MB
__device__ float g_xnorm[NN];
__device__ float g_featn[KK];
__device__ float g_satt[KK];
__device__ float g_gates[KK];
__device__ ull   g_adj[KK][NN][NN/64];    // 2 MB
__device__ float g_logits[KK][NN];

__device__ __forceinline__ float epoch_to_float(const int* p) {
    int ei = *p;
    return (ei >= 0 && ei < 1000000) ? (float)ei : __int_as_float(ei);
}

// ---------------- 0: zero accumulators + adjacency ----------------
__global__ void k_zero() {
    size_t idx = (size_t)blockIdx.x * blockDim.x + threadIdx.x;
    size_t stride = (size_t)gridDim.x * blockDim.x;
    ull* p = &g_adj[0][0][0];
    const size_t tot = (size_t)KK * NN * (NN/64);
    for (size_t i = idx; i < tot; i += stride) p[i] = 0ull;
    if (idx < KK) { g_featn[idx] = 0.f; g_satt[idx] = 0.f; }
}

// ---------------- 1: xhat / xnorm ----------------
__global__ void k_xhat(const float* __restrict__ X) {
    int n = blockIdx.x, t = threadIdx.x;   // 128 threads
    __shared__ float red[128];
    float v = X[(size_t)n * DD + t];
    red[t] = v * v; __syncthreads();
    for (int s = 64; s > 0; s >>= 1) { if (t < s) red[t] += red[t + s]; __syncthreads(); }
    float norm = sqrtf(red[0]);
    float inv = 1.f / fmaxf(norm, 1e-8f);
    g_xhat[n][t] = v * inv;
    if (t == 0) g_xnorm[n] = norm;
}

// ---------------- 2: edge stats + column bitsets (single H read, high MLP) ----------------
// Block: 256 threads = 16 edge-quads (4 edges each, float4) x 16 row-octants (128 rows).
__global__ __launch_bounds__(256) void k_edge(const float* __restrict__ H) {
    const int k = blockIdx.y, et = blockIdx.x;     // et in [0, EE/64)
    const int t = threadIdx.x;
    const int eq = t & 15, oct = t >> 4;
    const int e0 = et * 64 + eq * 4;
    const float* base = H + ((size_t)k * NN + (size_t)oct * 128) * EE + e0;

    ull m0a = 0, m1a = 0, m2a = 0, m3a = 0;
    ull m0b = 0, m1b = 0, m2b = 0, m3b = 0;
    #pragma unroll 4
    for (int r = 0; r < 64; r++) {
        float4 v = *(const float4*)(base + (size_t)r * EE);
        ull bit = 1ull << r;
        if (v.x > 0.f) m0a |= bit;
        if (v.y > 0.f) m1a |= bit;
        if (v.z > 0.f) m2a |= bit;
        if (v.w > 0.f) m3a |= bit;
    }
    #pragma unroll 4
    for (int r = 0; r < 64; r++) {
        float4 v = *(const float4*)(base + (size_t)(r + 64) * EE);
        ull bit = 1ull << r;
        if (v.x > 0.f) m0b |= bit;
        if (v.y > 0.f) m1b |= bit;
        if (v.z > 0.f) m2b |= bit;
        if (v.w > 0.f) m3b |= bit;
    }
    g_colbits[k][e0 + 0][oct * 2] = m0a;  g_colbits[k][e0 + 0][oct * 2 + 1] = m0b;
    g_colbits[k][e0 + 1][oct * 2] = m1a;  g_colbits[k][e0 + 1][oct * 2 + 1] = m1b;
    g_colbits[k][e0 + 2][oct * 2] = m2a;  g_colbits[k][e0 + 2][oct * 2 + 1] = m2b;
    g_colbits[k][e0 + 3][oct * 2] = m3a;  g_colbits[k][e0 + 3][oct * 2 + 1] = m3b;

    __shared__ short s_cnt[64][16];
    __shared__ short s_f[64][16];
    __shared__ short s_s[64][16];

    // per (edge, octant) stats
    {
        ull A[4] = {m0a, m1a, m2a, m3a};
        ull B[4] = {m0b, m1b, m2b, m3b};
        #pragma unroll
        for (int q = 0; q < 4; q++) {
            ull a = A[q], b = B[q];
            int ca = __popcll(a), cb = __popcll(b);
            int f = -1, s = -1;
            if (ca) {
                f = __ffsll((long long)a) - 1;
                if (ca >= 2) { ull a2 = a & (a - 1); s = __ffsll((long long)a2) - 1; }
                else if (cb) { s = 64 + __ffsll((long long)b) - 1; }
            } else if (cb) {
                f = 64 + __ffsll((long long)b) - 1;
                if (cb >= 2) { ull b2 = b & (b - 1); s = 64 + __ffsll((long long)b2) - 1; }
            }
            s_cnt[eq * 4 + q][oct] = (short)(ca + cb);
            s_f[eq * 4 + q][oct]   = (short)(oct * 128 + f);
            s_s[eq * 4 + q][oct]   = (short)(oct * 128 + s);
        }
    }
    __syncthreads();

    if (t < 64) {
        int e = et * 64 + t;
        int cnt = 0, i0 = 0, j0 = 0;
        #pragma unroll
        for (int o = 0; o < 16; o++) {
            int c = s_cnt[t][o];
            if (c > 0) {
                if (cnt == 0) { i0 = s_f[t][o]; if (c >= 2) j0 = s_s[t][o]; }
                else if (cnt == 1) { j0 = s_f[t][o]; }
                cnt += c;
            }
        }
        g_cnt[k][e] = cnt;
        g_ij[k][e] = make_int2(i0, j0);
        g_imp[k][e] = (e < 500) ? ((cnt >= 2) ? 0.f : 0.1f) : 0.f;
    }
}

// ---------------- 2b: scored-edge cosine importance (warp per edge) ----------------
__global__ __launch_bounds__(256) void k_imp(const float* __restrict__ H) {
    int w = (blockIdx.x * blockDim.x + threadIdx.x) >> 5;
    int lane = threadIdx.x & 31;
    int k = w >> 9, e = w & 511;              // KK*512 warps
    if (e >= 500) return;
    if (g_cnt[k][e] < 2) return;
    int2 ij = g_ij[k][e];
    float4 a = *(const float4*)&g_xhat[ij.x][lane * 4];
    float4 b = *(const float4*)&g_xhat[ij.y][lane * 4];
    float d = a.x * b.x + a.y * b.y + a.z * b.z + a.w * b.w;
    #pragma unroll
    for (int s = 16; s > 0; s >>= 1) d += __shfl_xor_sync(0xffffffffu, d, s);
    if (lane == 0) {
        const float* base = H + (size_t)k * NN * EE + e;
        float A = base[(size_t)ij.x * EE] * base[(size_t)ij.y * EE];
        g_imp[k][e] = A * d;
    }
}

// ---------------- 3: component MLP + attention (16-row tiles) ----------------
#define RT 16
__global__ __launch_bounds__(128) void k_gemm(
    const float* __restrict__ X,
    const float* __restrict__ w1, const float* __restrict__ b1,
    const float* __restrict__ w2, const float* __restrict__ b2,
    const float* __restrict__ aw1, const float* __restrict__ ab1,
    const float* __restrict__ aw2, const float* __restrict__ ab2)
{
    int k = blockIdx.y, nt = blockIdx.x, t = threadIdx.x;  // 128 threads
    __shared__ float Xs[DD][RT + 2];
    __shared__ float h1s[DD][RT + 2];
    __shared__ float a1s[64][RT + 2];
    __shared__ float red[128];

    // load RT rows of X, transposed
    for (int idx = t; idx < RT * DD; idx += 128) {
        int n = idx >> 7, d = idx & 127;
        Xs[d][n] = X[(size_t)(nt * RT + n) * DD + d];
    }
    __syncthreads();

    float acc[RT];
    #pragma unroll
    for (int n = 0; n < RT; n++) acc[n] = 0.f;
    const float* W1 = w1 + (size_t)k * DD * DD;
    for (int d = 0; d < DD; d++) {
        float w = W1[d * DD + t];
        #pragma unroll
        for (int n = 0; n < RT; n += 2) {
            float2 x2 = *(const float2*)&Xs[d][n];
            acc[n]   += x2.x * w;
            acc[n+1] += x2.y * w;
        }
    }
    {
        float bb = b1[k * DD + t];
        #pragma unroll
        for (int n = 0; n < RT; n++) h1s[t][n] = fmaxf(acc[n] + bb, 0.f);
    }
    __syncthreads();

    #pragma unroll
    for (int n = 0; n < RT; n++) acc[n] = 0.f;
    const float* W2 = w2 + (size_t)k * DD * DD;
    for (int d = 0; d < DD; d++) {
        float w = W2[d * DD + t];
        #pragma unroll
        for (int n = 0; n < RT; n += 2) {
            float2 x2 = *(const float2*)&h1s[d][n];
            acc[n]   += x2.x * w;
            acc[n+1] += x2.y * w;
        }
    }
    float fp = 0.f;
    {
        float b2v = b2[k * DD + t];
        #pragma unroll
        for (int n = 0; n < RT; n++) {
            float xk = acc[n] + b2v;
            fp += xk * xk;
            Xs[t][n] = xk;          // safe: Xs last read before prior sync
        }
    }
    __syncthreads();

    if (t < 64) {
        float a3[RT];
        #pragma unroll
        for (int n = 0; n < RT; n++) a3[n] = 0.f;
        const float* AW1 = aw1 + (size_t)k * DD * 64;
        for (int d = 0; d < DD; d++) {
            float w = AW1[d * 64 + t];
            #pragma unroll
            for (int n = 0; n < RT; n += 2) {
                float2 x2 = *(const float2*)&Xs[d][n];
                a3[n]   += x2.x * w;
                a3[n+1] += x2.y * w;
            }
        }
        float ab = ab1[k * 64 + t];
        #pragma unroll
        for (int n = 0; n < RT; n++) a1s[t][n] = fmaxf(a3[n] + ab, 0.f);
    }
    __syncthreads();

    float sattp = 0.f;
    if (t < RT) {
        int n = t;
        float s = ab2[k];
        const float* AW2 = aw2 + (size_t)k * 64;
        #pragma unroll 8
        for (int h = 0; h < 64; h++) s += a1s[h][n] * AW2[h];
        sattp = 1.f / (1.f + expf(-s));
    }

    red[t] = fp; __syncthreads();
    for (int s = 64; s > 0; s >>= 1) { if (t < s) red[t] += red[t + s]; __syncthreads(); }
    if (t == 0) atomicAdd(&g_featn[k], red[0]);
    __syncthreads();
    red[t] = sattp; __syncthreads();
    for (int s = 64; s > 0; s >>= 1) { if (t < s) red[t] += red[t + s]; __syncthreads(); }
    if (t == 0) atomicAdd(&g_satt[k], red[0]);
}

// ---------------- 4: component gates ----------------
__global__ void k_gates(const float* __restrict__ compW, const int* __restrict__ epochp,
                        float* __restrict__ out_gates)
{
    __shared__ float red[256];
    __shared__ float frob[KK];
    int t = threadIdx.x;
    for (int k = 0; k < KK; k++) {
        float s = 0.f;
        for (int i = t; i < DD * DD; i += 256) {
            float v = compW[(size_t)k * DD * DD + i];
            s += v * v;
        }
        red[t] = s; __syncthreads();
        for (int st = 128; st > 0; st >>= 1) { if (t < st) red[t] += red[t + st]; __syncthreads(); }
        if (t == 0) frob[k] = sqrtf(red[0]);
        __syncthreads();
    }
    if (t == 0) {
        float ep = epoch_to_float(epochp);
        float theta_c = TC0C + (1.f - expf(-LAMS * ep)) * (TCMAXC - TC0C);
        float imp[KK], pi[KK], g[KK];
        float m = -1e30f;
        for (int k = 0; k < KK; k++) {
            imp[k] = BETA * frob[k] * sqrtf(g_featn[k]) + (1.f - BETA) * (g_satt[k] / (float)NN);
            m = fmaxf(m, imp[k]);
        }
        float s = 0.f;
        for (int k = 0; k < KK; k++) { pi[k] = expf(imp[k] - m); s += pi[k]; }
        float gmax = -1.f; int am = 0;
        for (int k = 0; k < KK; k++) {
            pi[k] /= s;
            g[k] = fminf(fmaxf((pi[k] - theta_c) / EPSG + 0.5f, 0.f), 1.f);
            if (g[k] > gmax) { gmax = g[k]; am = k; }
        }
        g[am] = fmaxf(g[am], 1.f);
        for (int k = 0; k < KK; k++) { g_gates[k] = g[k]; out_gates[k] = g[k]; }
    }
}

// ---------------- 5: per-component edge softmax / eg ----------------
__global__ __launch_bounds__(512) void k_eg(const int* __restrict__ epochp,
                                            float* __restrict__ out_eg)
{
    const int k = blockIdx.x, t = threadIdx.x;
    __shared__ float pi[EE];
    __shared__ float red[512];
    __shared__ int redi[512];
    float lv[8];
    float vmax = -1e30f;
    #pragma unroll
    for (int r = 0; r < 8; r++) { lv[r] = g_imp[k][t + r * 512]; vmax = fmaxf(vmax, lv[r]); }
    red[t] = vmax; __syncthreads();
    for (int s = 256; s > 0; s >>= 1) { if (t < s) red[t] = fmaxf(red[t], red[t + s]); __syncthreads(); }
    const float M = red[0]; __syncthreads();

    float lsum = 0.f;
    #pragma unroll
    for (int r = 0; r < 8; r++) { float e_ = expf(lv[r] - M); pi[t + r * 512] = e_; lsum += e_; }
    red[t] = lsum; __syncthreads();
    for (int s = 256; s > 0; s >>= 1) { if (t < s) red[t] += red[t + s]; __syncthreads(); }
    const float S = red[0]; __syncthreads();
    const float invS = 1.f / S;

    float tsum = 0.f;
    #pragma unroll
    for (int r = 0; r < 8; r++) { float p = pi[t + r * 512] * invS; pi[t + r * 512] = p; tsum += p; }
    red[t] = tsum; __syncthreads();
    for (int s = 256; s > 0; s >>= 1) { if (t < s) red[t] += red[t + s]; __syncthreads(); }
    const float mean = red[0] / (float)EE; __syncthreads();

    float lvar = 0.f;
    #pragma unroll
    for (int r = 0; r < 8; r++) { float d = pi[t + r * 512] - mean; lvar += d * d; }
    red[t] = lvar; __syncthreads();
    for (int s = 256; s > 0; s >>= 1) { if (t < s) red[t] += red[t + s]; __syncthreads(); }
    const float stdv = sqrtf(red[0] / (float)(EE - 1)); __syncthreads();

    float ep = epoch_to_float(epochp);
    float theta_c = TC0C + (1.f - expf(-LAMS * ep)) * (TCMAXC - TC0C);
    float theta = fminf(theta_c, mean + stdv);

    float seg = 0.f, pmax = -1e30f; int pam = EE;
    #pragma unroll
    for (int r = 0; r < 8; r++) {
        int idx = t + r * 512;
        float p = pi[idx];
        float e_g = fminf(fmaxf((p - theta) / EPSG + 0.5f, 0.f), 1.f);
        lv[r] = e_g; seg += e_g;
        if (p > pmax) { pmax = p; pam = idx; }
    }
    red[t] = seg; __syncthreads();
    for (int s = 256; s > 0; s >>= 1) { if (t < s) red[t] += red[t + s]; __syncthreads(); }
    const float sumEg = red[0]; __syncthreads();

    red[t] = pmax; redi[t] = pam; __syncthreads();
    for (int s = 256; s > 0; s >>= 1) {
        if (t < s) {
            if (red[t + s] > red[t] || (red[t + s] == red[t] && redi[t + s] < redi[t])) {
                red[t] = red[t + s]; redi[t] = redi[t + s];
            }
        }
        __syncthreads();
    }
    const int am = redi[0];
    #pragma unroll
    for (int r = 0; r < 8; r++) {
        int idx = t + r * 512;
        float v = lv[r];
        if (sumEg < 1.f && idx == am) v = 1.f;
        g_eg[k][idx] = v;
        out_eg[(size_t)k * EE + idx] = v;
    }
}

// ---------------- 6: effective per-edge Hp value ----------------
__global__ void k_hval() {
    int gid = blockIdx.x * blockDim.x + threadIdx.x;
    int k = gid / EE, e = gid % EE;
    float g = g_gates[k];
    g_hval[k][e] = g * (g > 0.5f ? g_eg[k][e] : 1.f);
}

// ---------------- 7: write Hp from bitsets (write-only 134 MB) ----------------
__global__ __launch_bounds__(256) void k_hp(float* __restrict__ out) {
    int k = blockIdx.z, nt = blockIdx.y, et = blockIdx.x;
    int t = threadIdx.x;
    __shared__ ull bw[128];
    __shared__ float hv[128];
    if (t < 128) {
        hv[t] = g_hval[k][et * 128 + t];
        bw[t] = g_colbits[k][et * 128 + t][nt];
    }
    __syncthreads();
    #pragma unroll
    for (int r = 0; r < 8; r++) {
        int idx = t + r * 256;
        int nl = idx >> 5, q = idx & 31, el = q * 4;
        float4 v;
        v.x = ((bw[el + 0] >> nl) & 1ull) ? hv[el + 0] : 0.f;
        v.y = ((bw[el + 1] >> nl) & 1ull) ? hv[el + 1] : 0.f;
        v.z = ((bw[el + 2] >> nl) & 1ull) ? hv[el + 2] : 0.f;
        v.w = ((bw[el + 3] >> nl) & 1ull) ? hv[el + 3] : 0.f;
        *(float4*)&out[((size_t)k * NN + (size_t)nt * 64 + nl) * EE + et * 128 + el] = v;
    }
}

// ---------------- 8: sparse adjacency build (warp per edge) ----------------
__global__ __launch_bounds__(256) void k_adj() {
    int wId = (blockIdx.x * blockDim.x + threadIdx.x) >> 5;
    int lane = threadIdx.x & 31;
    int wl = threadIdx.x >> 5;
    int k = wId / EE, e = wId % EE;
    __shared__ unsigned short list[8][1024];
    __shared__ int scnt[8];
    if (g_hval[k][e] <= 0.f) return;
    if (g_cnt[k][e] < 2) return;
    if (lane == 0) scnt[wl] = 0;
    __syncwarp();
    ull m = g_colbits[k][e][lane];
    while (m) {
        int b = __ffsll((long long)m) - 1;
        m &= m - 1;
        int pos = atomicAdd(&scnt[wl], 1);
        if (pos < 1024) list[wl][pos] = (unsigned short)(lane * 64 + b);
    }
    __syncwarp();
    int cN = scnt[wl];
    if (cN > 1024) cN = 1024;
    for (int p = lane; p < cN * cN; p += 32) {
        int u = list[wl][p / cN];
        int v = list[wl][p % cN];
        if (u != v)
            atomicOr(&g_adj[k][u][v >> 6], 1ull << (v & 63));
    }
}

// ---------------- 9: neighbor sum -> logits (4-way ILP) ----------------
__global__ __launch_bounds__(128) void k_nsum() {
    int u = blockIdx.x, k = blockIdx.y, t = threadIdx.x;
    __shared__ unsigned short list[NN];
    __shared__ int s_deg;
    __shared__ float red[128];
    if (t < 32) {
        ull m = g_adj[k][u][t];
        int c = __popcll(m);
        int off = c;
        #pragma unroll
        for (int d = 1; d < 32; d <<= 1) {
            int x = __shfl_up_sync(0xffffffffu, off, d);
            if (t >= d) off += x;
        }
        off -= c;
        int pos = off;
        while (m) {
            int b = __ffsll((long long)m) - 1;
            m &= m - 1;
            list[pos++] = (unsigned short)(t * 64 + b);
        }
        if (t == 31) s_deg = off + c;
    }
    __syncthreads();
    int deg = s_deg;
    if (deg == 0) {
        if (t == 0) g_logits[k][u] = 0.f;
        return;
    }
    float a0 = 0.f, a1 = 0.f, a2 = 0.f, a3 = 0.f;
    int i = 0;
    for (; i + 4 <= deg; i += 4) {
        int l0 = list[i], l1 = list[i+1], l2 = list[i+2], l3 = list[i+3];
        a0 += g_xhat[l0][t];
        a1 += g_xhat[l1][t];
        a2 += g_xhat[l2][t];
        a3 += g_xhat[l3][t];
    }
    for (; i < deg; i++) a0 += g_xhat[list[i]][t];
    red[t] = g_xhat[u][t] * ((a0 + a1) + (a2 + a3));
    __syncthreads();
    for (int s = 64; s > 0; s >>= 1) { if (t < s) red[t] += red[t + s]; __syncthreads(); }
    if (t == 0) {
        float avg = red[0] / (float)deg;
        g_logits[k][u] = avg * g_xnorm[u];
    }
}

// ---------------- 10: npi softmax over nodes ----------------
__global__ __launch_bounds__(512) void k_npi(float* __restrict__ out_npi) {
    int k = blockIdx.x, t = threadIdx.x;
    __shared__ float red[512];
    float lv[4];
    float m = -1e30f;
    #pragma unroll
    for (int r = 0; r < 4; r++) { lv[r] = g_logits[k][t + r * 512]; m = fmaxf(m, lv[r]); }
    red[t] = m; __syncthreads();
    for (int s = 256; s > 0; s >>= 1) { if (t < s) red[t] = fmaxf(red[t], red[t + s]); __syncthreads(); }
    const float M = red[0]; __syncthreads();
    float ls = 0.f;
    #pragma unroll
    for (int r = 0; r < 4; r++) { lv[r] = expf(lv[r] - M); ls += lv[r]; }
    red[t] = ls; __syncthreads();
    for (int s = 256; s > 0; s >>= 1) { if (t < s) red[t] += red[t + s]; __syncthreads(); }
    const float invS = 1.f / red[0];
    #pragma unroll
    for (int r = 0; r < 4; r++)
        out_npi[(size_t)k * NN + t + r * 512] = lv[r] * invS;
}

// ---------------- launch ----------------
extern "C" void kernel_launch(void* const* d_in, const int* in_sizes, int n_in,
                              void* d_out, int out_size) {
    const float* H     = (const float*)d_in[0];
    const float* X     = (const float*)d_in[1];
    const int*   epoch = (const int*)  d_in[2];
    const float* w1    = (const float*)d_in[3];
    const float* b1    = (const float*)d_in[4];
    const float* w2    = (const float*)d_in[5];
    const float* b2    = (const float*)d_in[6];
    const float* compW = (const float*)d_in[7];
    const float* aw1   = (const float*)d_in[8];
    const float* ab1   = (const float*)d_in[9];
    const float* aw2   = (const float*)d_in[10];
    const float* ab2   = (const float*)d_in[11];
    float* out = (float*)d_out;

    const size_t OFF_G = (size_t)KK * NN * EE;
    const size_t OFF_E = OFF_G + KK;
    const size_t OFF_P = OFF_E + (size_t)KK * EE;

    k_zero<<<512, 256>>>();
    k_xhat<<<NN, 128>>>(X);
    k_edge<<<dim3(EE / 64, KK), 256>>>(H);
    k_imp<<<KK * 512 * 32 / 256, 256>>>(H);
    k_gemm<<<dim3(NN / RT, KK), 128>>>(X, w1, b1, w2, b2, aw1, ab1, aw2, ab2);
    k_gates<<<1, 256>>>(compW, epoch, out + OFF_G);
    k_eg<<<KK, 512>>>(epoch, out + OFF_E);
    k_hval<<<KK * EE / 256, 256>>>();
    k_hp<<<dim3(EE / 128, NN / 64, KK), 256>>>(out);
    k_adj<<<KK * EE / 8, 256>>>();
    k_nsum<<<dim3(NN, KK), 128>>>();
    k_npi<<<KK, 512>>>(out + OFF_P);
}

// round 3
// speedup vs baseline: 2.5867x; 1.1989x over previous
#include <cuda_runtime.h>
#include <cstdint>

#define KK 4
#define NN 2048
#define EE 4096
#define DD 128
#define NW 32
#define BETA  0.6f
#define EPSG  0.01f
#define LAMS  0.05f
#define TC0C  0.3f
#define TCMAXC 0.7f

typedef unsigned long long ull;

// ---------------- scratch (device globals; no allocation) ----------------
__device__ ull   g_colbits[KK][EE][NW];   // 4 MB
__device__ float g_imp[KK][EE];
__device__ float g_eg[KK][EE];
__device__ int   g_cnt[KK][EE];
__device__ int2  g_ij[KK][EE];
__device__ float g_xhat[NN][DD];          // 1 MB
__device__ float g_xnorm[NN];
__device__ float g_featn[KK];
__device__ float g_satt[KK];
__device__ float g_gates[KK];
__device__ ull   g_adj[KK][NN][NN/64];    // 2 MB
__device__ float g_logits[KK][NN];

__device__ __forceinline__ float epoch_to_float(const int* p) {
    int ei = *p;
    return (ei >= 0 && ei < 1000000) ? (float)ei : __int_as_float(ei);
}

__device__ __forceinline__ ull pack2(float x) {
    ull r;
    unsigned u = __float_as_uint(x);
    asm("mov.b64 %0, {%1, %1};" : "=l"(r) : "r"(u));
    return r;
}
__device__ __forceinline__ void unpack2(ull v, float& lo, float& hi) {
    unsigned a, b;
    asm("mov.b64 {%0, %1}, %2;" : "=r"(a), "=r"(b) : "l"(v));
    lo = __uint_as_float(a); hi = __uint_as_float(b);
}
__device__ __forceinline__ void fma2(ull& acc, ull x, ull w) {
    asm("fma.rn.f32x2 %0, %1, %2, %0;" : "+l"(acc) : "l"(x), "l"(w));
}

// ---------------- 1: init (adj zero + xhat/xnorm) ----------------
__global__ __launch_bounds__(128) void k_init(const float* __restrict__ X) {
    int n = blockIdx.x, t = threadIdx.x;
    ((ull*)g_adj)[(size_t)n * 128 + t] = 0ull;
    if (n == 0 && t < KK) { g_featn[t] = 0.f; g_satt[t] = 0.f; }
    __shared__ float red[128];
    float v = X[(size_t)n * DD + t];
    red[t] = v * v; __syncthreads();
    for (int s = 64; s > 0; s >>= 1) { if (t < s) red[t] += red[t + s]; __syncthreads(); }
    float norm = sqrtf(red[0]);
    float inv = 1.f / fmaxf(norm, 1e-8f);
    g_xhat[n][t] = v * inv;
    if (t == 0) g_xnorm[n] = norm;
}

// ---------------- 2: edge stats + bitsets + fused cosine importance ----------------
__global__ __launch_bounds__(256) void k_edge(const float* __restrict__ H) {
    const int k = blockIdx.y, et = blockIdx.x;     // et in [0, EE/64)
    const int t = threadIdx.x;
    const int eq = t & 15, oct = t >> 4;
    const int e0 = et * 64 + eq * 4;
    const float* base = H + ((size_t)k * NN + (size_t)oct * 128) * EE + e0;

    ull m0a = 0, m1a = 0, m2a = 0, m3a = 0;
    ull m0b = 0, m1b = 0, m2b = 0, m3b = 0;
    #pragma unroll 4
    for (int r = 0; r < 64; r++) {
        float4 v = *(const float4*)(base + (size_t)r * EE);
        ull bit = 1ull << r;
        if (v.x > 0.f) m0a |= bit;
        if (v.y > 0.f) m1a |= bit;
        if (v.z > 0.f) m2a |= bit;
        if (v.w > 0.f) m3a |= bit;
    }
    #pragma unroll 4
    for (int r = 0; r < 64; r++) {
        float4 v = *(const float4*)(base + (size_t)(r + 64) * EE);
        ull bit = 1ull << r;
        if (v.x > 0.f) m0b |= bit;
        if (v.y > 0.f) m1b |= bit;
        if (v.z > 0.f) m2b |= bit;
        if (v.w > 0.f) m3b |= bit;
    }
    g_colbits[k][e0 + 0][oct * 2] = m0a;  g_colbits[k][e0 + 0][oct * 2 + 1] = m0b;
    g_colbits[k][e0 + 1][oct * 2] = m1a;  g_colbits[k][e0 + 1][oct * 2 + 1] = m1b;
    g_colbits[k][e0 + 2][oct * 2] = m2a;  g_colbits[k][e0 + 2][oct * 2 + 1] = m2b;
    g_colbits[k][e0 + 3][oct * 2] = m3a;  g_colbits[k][e0 + 3][oct * 2 + 1] = m3b;

    __shared__ short s_cnt[64][16];
    __shared__ short s_f[64][16];
    __shared__ short s_s[64][16];
    __shared__ int fi[64], fj[64], fc[64];

    {
        ull A[4] = {m0a, m1a, m2a, m3a};
        ull B[4] = {m0b, m1b, m2b, m3b};
        #pragma unroll
        for (int q = 0; q < 4; q++) {
            ull a = A[q], b = B[q];
            int ca = __popcll(a), cb = __popcll(b);
            int f = -1, s = -1;
            if (ca) {
                f = __ffsll((long long)a) - 1;
                if (ca >= 2) { ull a2 = a & (a - 1); s = __ffsll((long long)a2) - 1; }
                else if (cb) { s = 64 + __ffsll((long long)b) - 1; }
            } else if (cb) {
                f = 64 + __ffsll((long long)b) - 1;
                if (cb >= 2) { ull b2 = b & (b - 1); s = 64 + __ffsll((long long)b2) - 1; }
            }
            s_cnt[eq * 4 + q][oct] = (short)(ca + cb);
            s_f[eq * 4 + q][oct]   = (short)(oct * 128 + f);
            s_s[eq * 4 + q][oct]   = (short)(oct * 128 + s);
        }
    }
    __syncthreads();

    if (t < 64) {
        int e = et * 64 + t;
        int cnt = 0, i0 = 0, j0 = 0;
        #pragma unroll
        for (int o = 0; o < 16; o++) {
            int c = s_cnt[t][o];
            if (c > 0) {
                if (cnt == 0) { i0 = s_f[t][o]; if (c >= 2) j0 = s_s[t][o]; }
                else if (cnt == 1) { j0 = s_f[t][o]; }
                cnt += c;
            }
        }
        g_cnt[k][e] = cnt;
        g_ij[k][e] = make_int2(i0, j0);
        fi[t] = i0; fj[t] = j0; fc[t] = cnt;
        g_imp[k][e] = (e < 500) ? ((cnt >= 2) ? 0.f : 0.1f) : 0.f;
    }
    __syncthreads();

    // fused cosine importance for scored edges (e < 500)
    if (et < 8) {
        int wl = t >> 5, lane = t & 31;
        for (int q = wl; q < 64; q += 8) {
            int e = et * 64 + q;
            if (e >= 500) continue;
            if (fc[q] < 2) continue;
            int i0 = fi[q], j0 = fj[q];
            float4 a = *(const float4*)&g_xhat[i0][lane * 4];
            float4 b = *(const float4*)&g_xhat[j0][lane * 4];
            float d = a.x * b.x + a.y * b.y + a.z * b.z + a.w * b.w;
            #pragma unroll
            for (int s = 16; s > 0; s >>= 1) d += __shfl_xor_sync(0xffffffffu, d, s);
            if (lane == 0) {
                const float* hb = H + (size_t)k * NN * EE + e;
                float A = hb[(size_t)i0 * EE] * hb[(size_t)j0 * EE];
                g_imp[k][e] = A * d;
            }
        }
    }
}

// ---------------- 3: component MLP + attention (f32x2 register tiles) ----------------
// block: 128 threads, 32 rows x 128 outs; thread = 4 rows x 8 outs.
// dynamic smem: Xs[128][36] | Hs[128][36] | Ws[4096]  (As, red overlay)
#define GM 32
#define XST 36
#define SM_BYTES ((4608 + 4608 + 4096) * 4)

// one 128->128 layer: in (smem, [d][XST]), W (global [128][128]), bias; out to smem transposed.
// returns per-thread sum of squares of outputs if sq.
__device__ __forceinline__ float layer128(const float* __restrict__ Xin,
                                          float* __restrict__ Ws,
                                          float* __restrict__ Xout,
                                          const float* __restrict__ Wg,
                                          const float* __restrict__ bg,
                                          bool relu, bool sq, int t)
{
    const int tr = t >> 4, tc = t & 15;
    const int r0 = tr * 4, o0 = tc * 8;
    ull acc2[4][4];
    #pragma unroll
    for (int a = 0; a < 4; a++)
        #pragma unroll
        for (int b = 0; b < 4; b++) acc2[a][b] = 0ull;

    for (int dc = 0; dc < 4; dc++) {
        __syncthreads();
        #pragma unroll
        for (int i = 0; i < 8; i++)
            ((float4*)Ws)[t + i * 128] = ((const float4*)Wg)[dc * 1024 + t + i * 128];
        __syncthreads();
        #pragma unroll 8
        for (int dl = 0; dl < 32; dl++) {
            int d = dc * 32 + dl;
            float4 xv = *(const float4*)&Xin[d * XST + r0];
            ull xb0 = pack2(xv.x), xb1 = pack2(xv.y), xb2 = pack2(xv.z), xb3 = pack2(xv.w);
            const ull* wrow = (const ull*)&Ws[dl * 128 + o0];
            ull w0 = wrow[0], w1 = wrow[1], w2 = wrow[2], w3 = wrow[3];
            fma2(acc2[0][0], xb0, w0); fma2(acc2[0][1], xb0, w1);
            fma2(acc2[0][2], xb0, w2); fma2(acc2[0][3], xb0, w3);
            fma2(acc2[1][0], xb1, w0); fma2(acc2[1][1], xb1, w1);
            fma2(acc2[1][2], xb1, w2); fma2(acc2[1][3], xb1, w3);
            fma2(acc2[2][0], xb2, w0); fma2(acc2[2][1], xb2, w1);
            fma2(acc2[2][2], xb2, w2); fma2(acc2[2][3], xb2, w3);
            fma2(acc2[3][0], xb3, w0); fma2(acc2[3][1], xb3, w1);
            fma2(acc2[3][2], xb3, w2); fma2(acc2[3][3], xb3, w3);
        }
    }
    __syncthreads();
    float fp = 0.f;
    #pragma unroll
    for (int rr = 0; rr < 4; rr++) {
        #pragma unroll
        for (int op = 0; op < 4; op++) {
            float lo, hi;
            unpack2(acc2[rr][op], lo, hi);
            float v0 = lo + bg[o0 + 2 * op];
            float v1 = hi + bg[o0 + 2 * op + 1];
            if (relu) { v0 = fmaxf(v0, 0.f); v1 = fmaxf(v1, 0.f); }
            if (sq) fp += v0 * v0 + v1 * v1;
            Xout[(o0 + 2 * op) * XST + r0 + rr]     = v0;
            Xout[(o0 + 2 * op + 1) * XST + r0 + rr] = v1;
        }
    }
    return fp;
}

__global__ __launch_bounds__(128) void k_gemm(
    const float* __restrict__ X,
    const float* __restrict__ w1, const float* __restrict__ b1,
    const float* __restrict__ w2, const float* __restrict__ b2,
    const float* __restrict__ aw1, const float* __restrict__ ab1,
    const float* __restrict__ aw2, const float* __restrict__ ab2)
{
    extern __shared__ float sm[];
    float* Xs = sm;                 // 4608
    float* Hs = sm + 4608;          // 4608
    float* Ws = sm + 9216;          // 4096
    float* As = Ws;                 // overlay (att activations, stride 33)
    float* red = Hs;                // overlay (final reductions)

    const int k = blockIdx.y, nt = blockIdx.x, t = threadIdx.x;

    // load X tile transposed
    for (int idx = t; idx < 1024; idx += 128) {
        int row = idx >> 5, dq = idx & 31;
        float4 v = ((const float4*)X)[((size_t)(nt * GM + row)) * 32 + dq];
        Xs[(dq * 4 + 0) * XST + row] = v.x;
        Xs[(dq * 4 + 1) * XST + row] = v.y;
        Xs[(dq * 4 + 2) * XST + row] = v.z;
        Xs[(dq * 4 + 3) * XST + row] = v.w;
    }
    __syncthreads();

    layer128(Xs, Ws, Hs, w1 + (size_t)k * DD * DD, b1 + k * DD, true, false, t);
    __syncthreads();
    float fp = layer128(Hs, Ws, Xs, w2 + (size_t)k * DD * DD, b2 + k * DD, false, true, t);
    __syncthreads();

    // att layer 1: 128 -> 64, input Xs (Xk transposed), plain fp32
    const int tcA = t & 7, trA = t >> 3;
    const int oA = tcA * 8, rA = trA * 2;
    float aacc[2][8];
    #pragma unroll
    for (int a = 0; a < 2; a++)
        #pragma unroll
        for (int b = 0; b < 8; b++) aacc[a][b] = 0.f;
    const float* AWg = aw1 + (size_t)k * DD * 64;
    for (int dc = 0; dc < 4; dc++) {
        __syncthreads();
        #pragma unroll
        for (int i = 0; i < 4; i++)
            ((float4*)Ws)[t + i * 128] = ((const float4*)AWg)[dc * 512 + t + i * 128];
        __syncthreads();
        #pragma unroll 8
        for (int dl = 0; dl < 32; dl++) {
            int d = dc * 32 + dl;
            float2 xv = *(const float2*)&Xs[d * XST + rA];
            float4 w0 = *(const float4*)&Ws[dl * 64 + oA];
            float4 w1v = *(const float4*)&Ws[dl * 64 + oA + 4];
            aacc[0][0] += xv.x * w0.x;  aacc[0][1] += xv.x * w0.y;
            aacc[0][2] += xv.x * w0.z;  aacc[0][3] += xv.x * w0.w;
            aacc[0][4] += xv.x * w1v.x; aacc[0][5] += xv.x * w1v.y;
            aacc[0][6] += xv.x * w1v.z; aacc[0][7] += xv.x * w1v.w;
            aacc[1][0] += xv.y * w0.x;  aacc[1][1] += xv.y * w0.y;
            aacc[1][2] += xv.y * w0.z;  aacc[1][3] += xv.y * w0.w;
            aacc[1][4] += xv.y * w1v.x; aacc[1][5] += xv.y * w1v.y;
            aacc[1][6] += xv.y * w1v.z; aacc[1][7] += xv.y * w1v.w;
        }
    }
    __syncthreads();   // all att1 reads of Ws done before As overlay writes
    #pragma unroll
    for (int rr = 0; rr < 2; rr++)
        #pragma unroll
        for (int oo = 0; oo < 8; oo++)
            As[(oA + oo) * 33 + rA + rr] = fmaxf(aacc[rr][oo] + ab1[k * 64 + oA + oo], 0.f);
    __syncthreads();

    // att layer 2 + sigmoid (rows 0..31 of tile)
    float sattp = 0.f;
    if (t < GM) {
        float s = ab2[k];
        const float* AW2 = aw2 + (size_t)k * 64;
        #pragma unroll 8
        for (int h = 0; h < 64; h++) s += As[h * 33 + t] * AW2[h];
        sattp = 1.f / (1.f + expf(-s));
    }

    __syncthreads();   // Hs reads (layer2) all complete; reuse as red
    red[t] = fp; __syncthreads();
    for (int s = 64; s > 0; s >>= 1) { if (t < s) red[t] += red[t + s]; __syncthreads(); }
    if (t == 0) atomicAdd(&g_featn[k], red[0]);
    __syncthreads();
    red[t] = sattp; __syncthreads();
    for (int s = 64; s > 0; s >>= 1) { if (t < s) red[t] += red[t + s]; __syncthreads(); }
    if (t == 0) atomicAdd(&g_satt[k], red[0]);
}

// ---------------- 4: gates (block 0) + edge softmax/eg (blocks 1..K) ----------------
__global__ __launch_bounds__(512) void k_gateseg(
    const float* __restrict__ compW, const int* __restrict__ epochp,
    float* __restrict__ out_gates, float* __restrict__ out_eg)
{
    const int t = threadIdx.x;
    if (blockIdx.x == 0) {
        __shared__ float red[512];
        __shared__ float frob[KK];
        for (int k = 0; k < KK; k++) {
            float s = 0.f;
            for (int i = t; i < DD * DD; i += 512) {
                float v = compW[(size_t)k * DD * DD + i];
                s += v * v;
            }
            red[t] = s; __syncthreads();
            for (int st = 256; st > 0; st >>= 1) { if (t < st) red[t] += red[t + st]; __syncthreads(); }
            if (t == 0) frob[k] = sqrtf(red[0]);
            __syncthreads();
        }
        if (t == 0) {
            float ep = epoch_to_float(epochp);
            float theta_c = TC0C + (1.f - expf(-LAMS * ep)) * (TCMAXC - TC0C);
            float imp[KK], pi[KK], g[KK];
            float m = -1e30f;
            for (int k = 0; k < KK; k++) {
                imp[k] = BETA * frob[k] * sqrtf(g_featn[k]) + (1.f - BETA) * (g_satt[k] / (float)NN);
                m = fmaxf(m, imp[k]);
            }
            float s = 0.f;
            for (int k = 0; k < KK; k++) { pi[k] = expf(imp[k] - m); s += pi[k]; }
            float gmax = -1.f; int am = 0;
            for (int k = 0; k < KK; k++) {
                pi[k] /= s;
                g[k] = fminf(fmaxf((pi[k] - theta_c) / EPSG + 0.5f, 0.f), 1.f);
                if (g[k] > gmax) { gmax = g[k]; am = k; }
            }
            g[am] = fmaxf(g[am], 1.f);
            for (int k = 0; k < KK; k++) { g_gates[k] = g[k]; out_gates[k] = g[k]; }
        }
        return;
    }

    const int k = blockIdx.x - 1;
    __shared__ float pi[EE];
    __shared__ float red[512];
    __shared__ int redi[512];
    float lv[8];
    float vmax = -1e30f;
    #pragma unroll
    for (int r = 0; r < 8; r++) { lv[r] = g_imp[k][t + r * 512]; vmax = fmaxf(vmax, lv[r]); }
    red[t] = vmax; __syncthreads();
    for (int s = 256; s > 0; s >>= 1) { if (t < s) red[t] = fmaxf(red[t], red[t + s]); __syncthreads(); }
    const float M = red[0]; __syncthreads();

    float lsum = 0.f;
    #pragma unroll
    for (int r = 0; r < 8; r++) { float e_ = expf(lv[r] - M); pi[t + r * 512] = e_; lsum += e_; }
    red[t] = lsum; __syncthreads();
    for (int s = 256; s > 0; s >>= 1) { if (t < s) red[t] += red[t + s]; __syncthreads(); }
    const float S = red[0]; __syncthreads();
    const float invS = 1.f / S;

    float tsum = 0.f;
    #pragma unroll
    for (int r = 0; r < 8; r++) { float p = pi[t + r * 512] * invS; pi[t + r * 512] = p; tsum += p; }
    red[t] = tsum; __syncthreads();
    for (int s = 256; s > 0; s >>= 1) { if (t < s) red[t] += red[t + s]; __syncthreads(); }
    const float mean = red[0] / (float)EE; __syncthreads();

    float lvar = 0.f;
    #pragma unroll
    for (int r = 0; r < 8; r++) { float d = pi[t + r * 512] - mean; lvar += d * d; }
    red[t] = lvar; __syncthreads();
    for (int s = 256; s > 0; s >>= 1) { if (t < s) red[t] += red[t + s]; __syncthreads(); }
    const float stdv = sqrtf(red[0] / (float)(EE - 1)); __syncthreads();

    float ep = epoch_to_float(epochp);
    float theta_c = TC0C + (1.f - expf(-LAMS * ep)) * (TCMAXC - TC0C);
    float theta = fminf(theta_c, mean + stdv);

    float seg = 0.f, pmax = -1e30f; int pam = EE;
    #pragma unroll
    for (int r = 0; r < 8; r++) {
        int idx = t + r * 512;
        float p = pi[idx];
        float e_g = fminf(fmaxf((p - theta) / EPSG + 0.5f, 0.f), 1.f);
        lv[r] = e_g; seg += e_g;
        if (p > pmax) { pmax = p; pam = idx; }
    }
    red[t] = seg; __syncthreads();
    for (int s = 256; s > 0; s >>= 1) { if (t < s) red[t] += red[t + s]; __syncthreads(); }
    const float sumEg = red[0]; __syncthreads();

    red[t] = pmax; redi[t] = pam; __syncthreads();
    for (int s = 256; s > 0; s >>= 1) {
        if (t < s) {
            if (red[t + s] > red[t] || (red[t + s] == red[t] && redi[t + s] < redi[t])) {
                red[t] = red[t + s]; redi[t] = redi[t + s];
            }
        }
        __syncthreads();
    }
    const int am = redi[0];
    #pragma unroll
    for (int r = 0; r < 8; r++) {
        int idx = t + r * 512;
        float v = lv[r];
        if (sumEg < 1.f && idx == am) v = 1.f;
        g_eg[k][idx] = v;
        out_eg[(size_t)k * EE + idx] = v;
    }
}

// ---------------- 5: write Hp from bitsets (hval inlined) ----------------
__global__ __launch_bounds__(256) void k_hp(float* __restrict__ out) {
    int k = blockIdx.z, nt = blockIdx.y, et = blockIdx.x;
    int t = threadIdx.x;
    __shared__ ull bw[128];
    __shared__ float hv[128];
    if (t < 128) {
        int e = et * 128 + t;
        float g = g_gates[k];
        float eg = g_eg[k][e];
        hv[t] = g * (g > 0.5f ? eg : 1.f);
        bw[t] = g_colbits[k][e][nt];
    }
    __syncthreads();
    #pragma unroll
    for (int r = 0; r < 8; r++) {
        int idx = t + r * 256;
        int nl = idx >> 5, q = idx & 31, el = q * 4;
        float4 v;
        v.x = ((bw[el + 0] >> nl) & 1ull) ? hv[el + 0] : 0.f;
        v.y = ((bw[el + 1] >> nl) & 1ull) ? hv[el + 1] : 0.f;
        v.z = ((bw[el + 2] >> nl) & 1ull) ? hv[el + 2] : 0.f;
        v.w = ((bw[el + 3] >> nl) & 1ull) ? hv[el + 3] : 0.f;
        *(float4*)&out[((size_t)k * NN + (size_t)nt * 64 + nl) * EE + et * 128 + el] = v;
    }
}

// ---------------- 6: sparse adjacency build (warp per edge, hval inlined) ----------------
__global__ __launch_bounds__(256) void k_adj() {
    int wId = (blockIdx.x * blockDim.x + threadIdx.x) >> 5;
    int lane = threadIdx.x & 31;
    int wl = threadIdx.x >> 5;
    int k = wId / EE, e = wId % EE;
    __shared__ unsigned short list[8][1024];
    __shared__ int scnt[8];
    float g = g_gates[k];
    if (g <= 0.f) return;
    if (g > 0.5f && g_eg[k][e] <= 0.f) return;
    if (g_cnt[k][e] < 2) return;
    if (lane == 0) scnt[wl] = 0;
    __syncwarp();
    ull m = g_colbits[k][e][lane];
    while (m) {
        int b = __ffsll((long long)m) - 1;
        m &= m - 1;
        int pos = atomicAdd(&scnt[wl], 1);
        if (pos < 1024) list[wl][pos] = (unsigned short)(lane * 64 + b);
    }
    __syncwarp();
    int cN = scnt[wl];
    if (cN > 1024) cN = 1024;
    for (int p = lane; p < cN * cN; p += 32) {
        int u = list[wl][p / cN];
        int v = list[wl][p % cN];
        if (u != v)
            atomicOr(&g_adj[k][u][v >> 6], 1ull << (v & 63));
    }
}

// ---------------- 7: neighbor sum -> logits (4 warps, float4 rows) ----------------
__global__ __launch_bounds__(128) void k_nsum() {
    int u = blockIdx.x, k = blockIdx.y, t = threadIdx.x;
    int w = t >> 5, lane = t & 31;
    __shared__ unsigned short list[NN];
    __shared__ int s_deg;
    __shared__ float wsum[4];
    if (t < 32) {
        ull m = g_adj[k][u][t];
        int c = __popcll(m);
        int off = c;
        #pragma unroll
        for (int d = 1; d < 32; d <<= 1) {
            int x = __shfl_up_sync(0xffffffffu, off, d);
            if (t >= d) off += x;
        }
        off -= c;
        int pos = off;
        while (m) {
            int b = __ffsll((long long)m) - 1;
            m &= m - 1;
            list[pos++] = (unsigned short)(t * 64 + b);
        }
        if (t == 31) s_deg = off + c;
    }
    __syncthreads();
    int deg = s_deg;
    if (deg == 0) {
        if (t == 0) g_logits[k][u] = 0.f;
        return;
    }
    float4 acc = make_float4(0.f, 0.f, 0.f, 0.f);
    for (int i = w; i < deg; i += 4) {
        int v = list[i];
        float4 x = *(const float4*)&g_xhat[v][lane * 4];
        acc.x += x.x; acc.y += x.y; acc.z += x.z; acc.w += x.w;
    }
    float4 uf = *(const float4*)&g_xhat[u][lane * 4];
    float d = acc.x * uf.x + acc.y * uf.y + acc.z * uf.z + acc.w * uf.w;
    #pragma unroll
    for (int s = 16; s > 0; s >>= 1) d += __shfl_xor_sync(0xffffffffu, d, s);
    if (lane == 0) wsum[w] = d;
    __syncthreads();
    if (t == 0) {
        float tot = (wsum[0] + wsum[1]) + (wsum[2] + wsum[3]);
        g_logits[k][u] = (tot / (float)deg) * g_xnorm[u];
    }
}

// ---------------- 8: npi softmax over nodes ----------------
__global__ __launch_bounds__(512) void k_npi(float* __restrict__ out_npi) {
    int k = blockIdx.x, t = threadIdx.x;
    __shared__ float red[512];
    float lv[4];
    float m = -1e30f;
    #pragma unroll
    for (int r = 0; r < 4; r++) { lv[r] = g_logits[k][t + r * 512]; m = fmaxf(m, lv[r]); }
    red[t] = m; __syncthreads();
    for (int s = 256; s > 0; s >>= 1) { if (t < s) red[t] = fmaxf(red[t], red[t + s]); __syncthreads(); }
    const float M = red[0]; __syncthreads();
    float ls = 0.f;
    #pragma unroll
    for (int r = 0; r < 4; r++) { lv[r] = expf(lv[r] - M); ls += lv[r]; }
    red[t] = ls; __syncthreads();
    for (int s = 256; s > 0; s >>= 1) { if (t < s) red[t] += red[t + s]; __syncthreads(); }
    const float invS = 1.f / red[0];
    #pragma unroll
    for (int r = 0; r < 4; r++)
        out_npi[(size_t)k * NN + t + r * 512] = lv[r] * invS;
}

// ---------------- launch ----------------
extern "C" void kernel_launch(void* const* d_in, const int* in_sizes, int n_in,
                              void* d_out, int out_size) {
    const float* H     = (const float*)d_in[0];
    const float* X     = (const float*)d_in[1];
    const int*   epoch = (const int*)  d_in[2];
    const float* w1    = (const float*)d_in[3];
    const float* b1    = (const float*)d_in[4];
    const float* w2    = (const float*)d_in[5];
    const float* b2    = (const float*)d_in[6];
    const float* compW = (const float*)d_in[7];
    const float* aw1   = (const float*)d_in[8];
    const float* ab1   = (const float*)d_in[9];
    const float* aw2   = (const float*)d_in[10];
    const float* ab2   = (const float*)d_in[11];
    float* out = (float*)d_out;

    const size_t OFF_G = (size_t)KK * NN * EE;
    const size_t OFF_E = OFF_G + KK;
    const size_t OFF_P = OFF_E + (size_t)KK * EE;

    cudaFuncSetAttribute(k_gemm, cudaFuncAttributeMaxDynamicSharedMemorySize, SM_BYTES);

    k_init<<<NN, 128>>>(X);
    k_edge<<<dim3(EE / 64, KK), 256>>>(H);
    k_gemm<<<dim3(NN / GM, KK), 128, SM_BYTES>>>(X, w1, b1, w2, b2, aw1, ab1, aw2, ab2);
    k_gateseg<<<KK + 1, 512>>>(compW, epoch, out + OFF_G, out + OFF_E);
    k_hp<<<dim3(EE / 128, NN / 64, KK), 256>>>(out);
    k_adj<<<KK * EE / 8, 256>>>();
    k_nsum<<<dim3(NN, KK), 128>>>();
    k_npi<<<KK, 512>>>(out + OFF_P);
}

// round 5
// speedup vs baseline: 3.4850x; 1.3473x over previous
#include <cuda_runtime.h>
#include <cstdint>

#define KK 4
#define NN 2048
#define EE 4096
#define DD 128
#define NW 32
#define BETA  0.6f
#define EPSG  0.01f
#define LAMS  0.05f
#define TC0C  0.3f
#define TCMAXC 0.7f

typedef unsigned long long ull;

// ---------------- scratch (device globals; no allocation) ----------------
__device__ ull   g_colbits[KK][EE][NW];   // 4 MB
__device__ float g_imp[KK][EE];
__device__ float g_eg[KK][EE];
__device__ int   g_cnt[KK][EE];
__device__ float g_xhat[NN][DD];          // 1 MB
__device__ float g_xnorm[NN];
__device__ float g_featn[KK];
__device__ float g_satt[KK];
__device__ float g_gates[KK];
__device__ ull   g_adj[KK][NN][NN/64];    // 2 MB
__device__ float g_logits[KK][NN];

__device__ __forceinline__ float epoch_to_float(const int* p) {
    int ei = *p;
    return (ei >= 0 && ei < 1000000) ? (float)ei : __int_as_float(ei);
}

__device__ __forceinline__ ull pack2(float x) {
    ull r;
    unsigned u = __float_as_uint(x);
    asm("mov.b64 %0, {%1, %1};" : "=l"(r) : "r"(u));
    return r;
}
__device__ __forceinline__ void unpack2(ull v, float& lo, float& hi) {
    unsigned a, b;
    asm("mov.b64 {%0, %1}, %2;" : "=r"(a), "=r"(b) : "l"(v));
    lo = __uint_as_float(a); hi = __uint_as_float(b);
}
__device__ __forceinline__ void fma2(ull& acc, ull x, ull w) {
    asm("fma.rn.f32x2 %0, %1, %2, %0;" : "+l"(acc) : "l"(x), "l"(w));
}

// ---------------- 1: init (adj zero + xhat/xnorm) ----------------
__global__ __launch_bounds__(128) void k_init(const float* __restrict__ X) {
    int n = blockIdx.x, t = threadIdx.x;
    ((ull*)g_adj)[(size_t)n * 128 + t] = 0ull;
    if (n == 0 && t < KK) { g_featn[t] = 0.f; g_satt[t] = 0.f; }
    __shared__ float red[128];
    float v = X[(size_t)n * DD + t];
    red[t] = v * v; __syncthreads();
    for (int s = 64; s > 0; s >>= 1) { if (t < s) red[t] += red[t + s]; __syncthreads(); }
    float norm = sqrtf(red[0]);
    float inv = 1.f / fmaxf(norm, 1e-8f);
    g_xhat[n][t] = v * inv;
    if (t == 0) g_xnorm[n] = norm;
}

// ---------------- 2: edge stats + bitsets + fused cosine importance ----------------
// Block: 256 threads = 8 edge-quads (4 edges, float4) x 32 row-words (64 rows each).
__global__ __launch_bounds__(256) void k_edge(const float* __restrict__ H) {
    const int k = blockIdx.y, et = blockIdx.x;     // et in [0, EE/32)
    const int t = threadIdx.x;
    const int eq = t & 7, oct = t >> 3;
    const int e0 = et * 32 + eq * 4;
    const float* base = H + ((size_t)k * NN + (size_t)oct * 64) * EE + e0;

    ull m0 = 0, m1 = 0, m2 = 0, m3 = 0;
    #pragma unroll 4
    for (int r = 0; r < 64; r++) {
        float4 v = *(const float4*)(base + (size_t)r * EE);
        ull bit = 1ull << r;
        if (v.x > 0.f) m0 |= bit;
        if (v.y > 0.f) m1 |= bit;
        if (v.z > 0.f) m2 |= bit;
        if (v.w > 0.f) m3 |= bit;
    }
    g_colbits[k][e0 + 0][oct] = m0;
    g_colbits[k][e0 + 1][oct] = m1;
    g_colbits[k][e0 + 2][oct] = m2;
    g_colbits[k][e0 + 3][oct] = m3;

    __shared__ short s_cnt[32][33];
    __shared__ short s_f[32][33];
    __shared__ short s_s[32][33];
    __shared__ int fi[32], fj[32], fc[32];

    {
        ull M[4] = {m0, m1, m2, m3};
        #pragma unroll
        for (int q = 0; q < 4; q++) {
            ull m = M[q];
            int c = __popcll(m);
            int f = c ? (oct * 64 + __ffsll((long long)m) - 1) : -1;
            int s2 = (c >= 2) ? (oct * 64 + __ffsll((long long)(m & (m - 1))) - 1) : -1;
            s_cnt[eq * 4 + q][oct] = (short)c;
            s_f[eq * 4 + q][oct]   = (short)f;
            s_s[eq * 4 + q][oct]   = (short)s2;
        }
    }
    __syncthreads();

    if (t < 32) {
        int e = et * 32 + t;
        int cnt = 0, i0 = 0, j0 = 0;
        #pragma unroll
        for (int o = 0; o < 32; o++) {
            int c = s_cnt[t][o];
            if (c > 0) {
                if (cnt == 0) { i0 = s_f[t][o]; if (c >= 2) j0 = s_s[t][o]; }
                else if (cnt == 1) { j0 = s_f[t][o]; }
                cnt += c;
            }
        }
        g_cnt[k][e] = cnt;
        fi[t] = i0; fj[t] = j0; fc[t] = cnt;
        g_imp[k][e] = (e < 500) ? ((cnt >= 2) ? 0.f : 0.1f) : 0.f;
    }
    __syncthreads();

    // fused cosine importance for scored edges (e < 500)
    if (et * 32 < 500) {
        int wl = t >> 5, lane = t & 31;
        for (int q = wl; q < 32; q += 8) {
            int e = et * 32 + q;
            if (e >= 500) continue;
            if (fc[q] < 2) continue;
            int i0 = fi[q], j0 = fj[q];
            float4 a = *(const float4*)&g_xhat[i0][lane * 4];
            float4 b = *(const float4*)&g_xhat[j0][lane * 4];
            float d = a.x * b.x + a.y * b.y + a.z * b.z + a.w * b.w;
            #pragma unroll
            for (int s = 16; s > 0; s >>= 1) d += __shfl_xor_sync(0xffffffffu, d, s);
            if (lane == 0) {
                const float* hb = H + (size_t)k * NN * EE + e;
                float A = hb[(size_t)i0 * EE] * hb[(size_t)j0 * EE];
                g_imp[k][e] = A * d;
            }
        }
    }
}

// ---------------- 3: component MLP + attention (f32x2 register tiles) ----------------
#define GM 32
#define XST 36
#define SM_BYTES ((4608 + 4608 + 4096) * 4)

__device__ __forceinline__ float layer128(const float* __restrict__ Xin,
                                          float* __restrict__ Ws,
                                          float* __restrict__ Xout,
                                          const float* __restrict__ Wg,
                                          const float* __restrict__ bg,
                                          bool relu, bool sq, int t)
{
    const int tr = t >> 4, tc = t & 15;
    const int r0 = tr * 4, o0 = tc * 8;
    ull acc2[4][4];
    #pragma unroll
    for (int a = 0; a < 4; a++)
        #pragma unroll
        for (int b = 0; b < 4; b++) acc2[a][b] = 0ull;

    for (int dc = 0; dc < 4; dc++) {
        __syncthreads();
        #pragma unroll
        for (int i = 0; i < 8; i++)
            ((float4*)Ws)[t + i * 128] = ((const float4*)Wg)[dc * 1024 + t + i * 128];
        __syncthreads();
        #pragma unroll 8
        for (int dl = 0; dl < 32; dl++) {
            int d = dc * 32 + dl;
            float4 xv = *(const float4*)&Xin[d * XST + r0];
            ull xb0 = pack2(xv.x), xb1 = pack2(xv.y), xb2 = pack2(xv.z), xb3 = pack2(xv.w);
            const ull* wrow = (const ull*)&Ws[dl * 128 + o0];
            ull w0 = wrow[0], w1 = wrow[1], w2 = wrow[2], w3 = wrow[3];
            fma2(acc2[0][0], xb0, w0); fma2(acc2[0][1], xb0, w1);
            fma2(acc2[0][2], xb0, w2); fma2(acc2[0][3], xb0, w3);
            fma2(acc2[1][0], xb1, w0); fma2(acc2[1][1], xb1, w1);
            fma2(acc2[1][2], xb1, w2); fma2(acc2[1][3], xb1, w3);
            fma2(acc2[2][0], xb2, w0); fma2(acc2[2][1], xb2, w1);
            fma2(acc2[2][2], xb2, w2); fma2(acc2[2][3], xb2, w3);
            fma2(acc2[3][0], xb3, w0); fma2(acc2[3][1], xb3, w1);
            fma2(acc2[3][2], xb3, w2); fma2(acc2[3][3], xb3, w3);
        }
    }
    __syncthreads();
    float fp = 0.f;
    #pragma unroll
    for (int rr = 0; rr < 4; rr++) {
        #pragma unroll
        for (int op = 0; op < 4; op++) {
            float lo, hi;
            unpack2(acc2[rr][op], lo, hi);
            float v0 = lo + bg[o0 + 2 * op];
            float v1 = hi + bg[o0 + 2 * op + 1];
            if (relu) { v0 = fmaxf(v0, 0.f); v1 = fmaxf(v1, 0.f); }
            if (sq) fp += v0 * v0 + v1 * v1;
            Xout[(o0 + 2 * op) * XST + r0 + rr]     = v0;
            Xout[(o0 + 2 * op + 1) * XST + r0 + rr] = v1;
        }
    }
    return fp;
}

__global__ __launch_bounds__(128) void k_gemm(
    const float* __restrict__ X,
    const float* __restrict__ w1, const float* __restrict__ b1,
    const float* __restrict__ w2, const float* __restrict__ b2,
    const float* __restrict__ aw1, const float* __restrict__ ab1,
    const float* __restrict__ aw2, const float* __restrict__ ab2)
{
    extern __shared__ float sm[];
    float* Xs = sm;
    float* Hs = sm + 4608;
    float* Ws = sm + 9216;
    float* As = Ws;
    float* red = Hs;

    const int k = blockIdx.y, nt = blockIdx.x, t = threadIdx.x;

    for (int idx = t; idx < 1024; idx += 128) {
        int row = idx >> 5, dq = idx & 31;
        float4 v = ((const float4*)X)[((size_t)(nt * GM + row)) * 32 + dq];
        Xs[(dq * 4 + 0) * XST + row] = v.x;
        Xs[(dq * 4 + 1) * XST + row] = v.y;
        Xs[(dq * 4 + 2) * XST + row] = v.z;
        Xs[(dq * 4 + 3) * XST + row] = v.w;
    }
    __syncthreads();

    layer128(Xs, Ws, Hs, w1 + (size_t)k * DD * DD, b1 + k * DD, true, false, t);
    __syncthreads();
    float fp = layer128(Hs, Ws, Xs, w2 + (size_t)k * DD * DD, b2 + k * DD, false, true, t);
    __syncthreads();

    const int tcA = t & 7, trA = t >> 3;
    const int oA = tcA * 8, rA = trA * 2;
    float aacc[2][8];
    #pragma unroll
    for (int a = 0; a < 2; a++)
        #pragma unroll
        for (int b = 0; b < 8; b++) aacc[a][b] = 0.f;
    const float* AWg = aw1 + (size_t)k * DD * 64;
    for (int dc = 0; dc < 4; dc++) {
        __syncthreads();
        #pragma unroll
        for (int i = 0; i < 4; i++)
            ((float4*)Ws)[t + i * 128] = ((const float4*)AWg)[dc * 512 + t + i * 128];
        __syncthreads();
        #pragma unroll 8
        for (int dl = 0; dl < 32; dl++) {
            int d = dc * 32 + dl;
            float2 xv = *(const float2*)&Xs[d * XST + rA];
            float4 w0 = *(const float4*)&Ws[dl * 64 + oA];
            float4 w1v = *(const float4*)&Ws[dl * 64 + oA + 4];
            aacc[0][0] += xv.x * w0.x;  aacc[0][1] += xv.x * w0.y;
            aacc[0][2] += xv.x * w0.z;  aacc[0][3] += xv.x * w0.w;
            aacc[0][4] += xv.x * w1v.x; aacc[0][5] += xv.x * w1v.y;
            aacc[0][6] += xv.x * w1v.z; aacc[0][7] += xv.x * w1v.w;
            aacc[1][0] += xv.y * w0.x;  aacc[1][1] += xv.y * w0.y;
            aacc[1][2] += xv.y * w0.z;  aacc[1][3] += xv.y * w0.w;
            aacc[1][4] += xv.y * w1v.x; aacc[1][5] += xv.y * w1v.y;
            aacc[1][6] += xv.y * w1v.z; aacc[1][7] += xv.y * w1v.w;
        }
    }
    __syncthreads();
    #pragma unroll
    for (int rr = 0; rr < 2; rr++)
        #pragma unroll
        for (int oo = 0; oo < 8; oo++)
            As[(oA + oo) * 33 + rA + rr] = fmaxf(aacc[rr][oo] + ab1[k * 64 + oA + oo], 0.f);
    __syncthreads();

    float sattp = 0.f;
    if (t < GM) {
        float s = ab2[k];
        const float* AW2 = aw2 + (size_t)k * 64;
        #pragma unroll 8
        for (int h = 0; h < 64; h++) s += As[h * 33 + t] * AW2[h];
        sattp = 1.f / (1.f + expf(-s));
    }

    __syncthreads();
    red[t] = fp; __syncthreads();
    for (int s = 64; s > 0; s >>= 1) { if (t < s) red[t] += red[t + s]; __syncthreads(); }
    if (t == 0) atomicAdd(&g_featn[k], red[0]);
    __syncthreads();
    red[t] = sattp; __syncthreads();
    for (int s = 64; s > 0; s >>= 1) { if (t < s) red[t] += red[t + s]; __syncthreads(); }
    if (t == 0) atomicAdd(&g_satt[k], red[0]);
}

// ---------------- 4: gates (block 0) + edge softmax/eg (blocks 1..K) ----------------
__global__ __launch_bounds__(512) void k_gateseg(
    const float* __restrict__ compW, const int* __restrict__ epochp,
    float* __restrict__ out_gates, float* __restrict__ out_eg)
{
    const int t = threadIdx.x, lane = t & 31, wid = t >> 5;
    __shared__ float sm[16];
    __shared__ int smi[16];

    if (blockIdx.x == 0) {
        // frob: 128 threads per k, parallel over k
        int k = t >> 7, tl = t & 127;
        float s = 0.f;
        const float* W = compW + (size_t)k * DD * DD;
        for (int i = tl; i < DD * DD; i += 128) { float v = W[i]; s += v * v; }
        #pragma unroll
        for (int d = 16; d > 0; d >>= 1) s += __shfl_xor_sync(0xffffffffu, s, d);
        if (lane == 0) sm[wid] = s;
        __syncthreads();
        if (t == 0) {
            float ep = epoch_to_float(epochp);
            float theta_c = TC0C + (1.f - expf(-LAMS * ep)) * (TCMAXC - TC0C);
            float imp[KK], pi[KK], g[KK];
            float m = -1e30f;
            for (int k2 = 0; k2 < KK; k2++) {
                float fr = sqrtf(sm[k2 * 4] + sm[k2 * 4 + 1] + sm[k2 * 4 + 2] + sm[k2 * 4 + 3]);
                imp[k2] = BETA * fr * sqrtf(g_featn[k2]) + (1.f - BETA) * (g_satt[k2] / (float)NN);
                m = fmaxf(m, imp[k2]);
            }
            float su = 0.f;
            for (int k2 = 0; k2 < KK; k2++) { pi[k2] = expf(imp[k2] - m); su += pi[k2]; }
            float gmax = -1.f; int am = 0;
            for (int k2 = 0; k2 < KK; k2++) {
                pi[k2] /= su;
                g[k2] = fminf(fmaxf((pi[k2] - theta_c) / EPSG + 0.5f, 0.f), 1.f);
                if (g[k2] > gmax) { gmax = g[k2]; am = k2; }
            }
            g[am] = fmaxf(g[am], 1.f);
            for (int k2 = 0; k2 < KK; k2++) { g_gates[k2] = g[k2]; out_gates[k2] = g[k2]; }
        }
        return;
    }

    const int k = blockIdx.x - 1;
    float lv[8];

    // NOTE: final butterfly covers sm[0..15] exactly once (xor distances 8..1
    // stay within a 16-lane group) — no correction factor.
    auto redsum = [&](float v) -> float {
        __syncthreads();
        #pragma unroll
        for (int d = 16; d > 0; d >>= 1) v += __shfl_xor_sync(0xffffffffu, v, d);
        if (lane == 0) sm[wid] = v;
        __syncthreads();
        if (wid == 0) {
            float x = sm[lane & 15];
            #pragma unroll
            for (int d = 8; d > 0; d >>= 1) x += __shfl_xor_sync(0xffffffffu, x, d);
            if (lane == 0) sm[0] = x;
        }
        __syncthreads();
        return sm[0];
    };
    auto redmax = [&](float v) -> float {
        __syncthreads();
        #pragma unroll
        for (int d = 16; d > 0; d >>= 1) v = fmaxf(v, __shfl_xor_sync(0xffffffffu, v, d));
        if (lane == 0) sm[wid] = v;
        __syncthreads();
        if (wid == 0) {
            float x = sm[lane & 15];
            #pragma unroll
            for (int d = 8; d > 0; d >>= 1) x = fmaxf(x, __shfl_xor_sync(0xffffffffu, x, d));
            if (lane == 0) sm[0] = x;
        }
        __syncthreads();
        return sm[0];
    };
    auto redargmax = [&](float v, int i) -> int {
        __syncthreads();
        #pragma unroll
        for (int d = 16; d > 0; d >>= 1) {
            float ov = __shfl_xor_sync(0xffffffffu, v, d);
            int   oi = __shfl_xor_sync(0xffffffffu, i, d);
            if (ov > v || (ov == v && oi < i)) { v = ov; i = oi; }
        }
        if (lane == 0) { sm[wid] = v; smi[wid] = i; }
        __syncthreads();
        if (wid == 0) {
            float x = sm[lane & 15]; int xi = smi[lane & 15];
            #pragma unroll
            for (int d = 8; d > 0; d >>= 1) {
                float ov = __shfl_xor_sync(0xffffffffu, x, d);
                int   oi = __shfl_xor_sync(0xffffffffu, xi, d);
                if (ov > x || (ov == x && oi < xi)) { x = ov; xi = oi; }
            }
            if (lane == 0) smi[0] = xi;
        }
        __syncthreads();
        return smi[0];
    };

    float vmax = -1e30f;
    #pragma unroll
    for (int r = 0; r < 8; r++) { lv[r] = g_imp[k][t + r * 512]; vmax = fmaxf(vmax, lv[r]); }
    const float M = redmax(vmax);

    float lsum = 0.f;
    #pragma unroll
    for (int r = 0; r < 8; r++) { lv[r] = expf(lv[r] - M); lsum += lv[r]; }
    const float invS = 1.f / redsum(lsum);

    float tsum = 0.f;
    #pragma unroll
    for (int r = 0; r < 8; r++) { lv[r] *= invS; tsum += lv[r]; }
    const float mean = redsum(tsum) / (float)EE;

    float lvar = 0.f;
    #pragma unroll
    for (int r = 0; r < 8; r++) { float d = lv[r] - mean; lvar += d * d; }
    const float stdv = sqrtf(redsum(lvar) / (float)(EE - 1));

    float ep = epoch_to_float(epochp);
    float theta_c = TC0C + (1.f - expf(-LAMS * ep)) * (TCMAXC - TC0C);
    float theta = fminf(theta_c, mean + stdv);

    float seg = 0.f, pmax = -1e30f; int pam = EE;
    float le[8];
    #pragma unroll
    for (int r = 0; r < 8; r++) {
        int idx = t + r * 512;
        float p = lv[r];
        float e_g = fminf(fmaxf((p - theta) / EPSG + 0.5f, 0.f), 1.f);
        le[r] = e_g; seg += e_g;
        if (p > pmax) { pmax = p; pam = idx; }
    }
    const float sumEg = redsum(seg);
    const int am = redargmax(pmax, pam);

    #pragma unroll
    for (int r = 0; r < 8; r++) {
        int idx = t + r * 512;
        float v = le[r];
        if (sumEg < 1.f && idx == am) v = 1.f;
        g_eg[k][idx] = v;
        out_eg[(size_t)k * EE + idx] = v;
    }
}

// ---------------- 5: write Hp from bitsets (hval inlined) ----------------
__global__ __launch_bounds__(256) void k_hp(float* __restrict__ out) {
    int k = blockIdx.z, nt = blockIdx.y, et = blockIdx.x;
    int t = threadIdx.x;
    __shared__ ull bw[128];
    __shared__ float hv[128];
    if (t < 128) {
        int e = et * 128 + t;
        float g = g_gates[k];
        float eg = g_eg[k][e];
        hv[t] = g * (g > 0.5f ? eg : 1.f);
        bw[t] = g_colbits[k][e][nt];
    }
    __syncthreads();
    #pragma unroll
    for (int r = 0; r < 8; r++) {
        int idx = t + r * 256;
        int nl = idx >> 5, q = idx & 31, el = q * 4;
        float4 v;
        v.x = ((bw[el + 0] >> nl) & 1ull) ? hv[el + 0] : 0.f;
        v.y = ((bw[el + 1] >> nl) & 1ull) ? hv[el + 1] : 0.f;
        v.z = ((bw[el + 2] >> nl) & 1ull) ? hv[el + 2] : 0.f;
        v.w = ((bw[el + 3] >> nl) & 1ull) ? hv[el + 3] : 0.f;
        *(float4*)&out[((size_t)k * NN + (size_t)nt * 64 + nl) * EE + et * 128 + el] = v;
    }
}

// ---------------- 6: sparse adjacency build (warp per edge) ----------------
__global__ __launch_bounds__(256) void k_adj() {
    int wId = (blockIdx.x * blockDim.x + threadIdx.x) >> 5;
    int lane = threadIdx.x & 31;
    int wl = threadIdx.x >> 5;
    int k = wId / EE, e = wId % EE;
    __shared__ unsigned short list[8][1024];
    __shared__ int scnt[8];
    float g = g_gates[k];
    if (g <= 0.f) return;
    if (g > 0.5f && g_eg[k][e] <= 0.f) return;
    if (g_cnt[k][e] < 2) return;
    if (lane == 0) scnt[wl] = 0;
    __syncwarp();
    ull m = g_colbits[k][e][lane];
    while (m) {
        int b = __ffsll((long long)m) - 1;
        m &= m - 1;
        int pos = atomicAdd(&scnt[wl], 1);
        if (pos < 1024) list[wl][pos] = (unsigned short)(lane * 64 + b);
    }
    __syncwarp();
    int cN = scnt[wl];
    if (cN > 1024) cN = 1024;
    for (int p = lane; p < cN * cN; p += 32) {
        int u = list[wl][p / cN];
        int v = list[wl][p % cN];
        if (u != v)
            atomicOr(&g_adj[k][u][v >> 6], 1ull << (v & 63));
    }
}

// ---------------- 7: neighbor sum -> logits (4 warps, float4 rows) ----------------
__global__ __launch_bounds__(128) void k_nsum() {
    int u = blockIdx.x, k = blockIdx.y, t = threadIdx.x;
    int w = t >> 5, lane = t & 31;
    __shared__ unsigned short list[NN];
    __shared__ int s_deg;
    __shared__ float wsum[4];
    if (t < 32) {
        ull m = g_adj[k][u][t];
        int c = __popcll(m);
        int off = c;
        #pragma unroll
        for (int d = 1; d < 32; d <<= 1) {
            int x = __shfl_up_sync(0xffffffffu, off, d);
            if (t >= d) off += x;
        }
        off -= c;
        int pos = off;
        while (m) {
            int b = __ffsll((long long)m) - 1;
            m &= m - 1;
            list[pos++] = (unsigned short)(t * 64 + b);
        }
        if (t == 31) s_deg = off + c;
    }
    __syncthreads();
    int deg = s_deg;
    if (deg == 0) {
        if (t == 0) g_logits[k][u] = 0.f;
        return;
    }
    float4 acc = make_float4(0.f, 0.f, 0.f, 0.f);
    for (int i = w; i < deg; i += 4) {
        int v = list[i];
        float4 x = *(const float4*)&g_xhat[v][lane * 4];
        acc.x += x.x; acc.y += x.y; acc.z += x.z; acc.w += x.w;
    }
    float4 uf = *(const float4*)&g_xhat[u][lane * 4];
    float d = acc.x * uf.x + acc.y * uf.y + acc.z * uf.z + acc.w * uf.w;
    #pragma unroll
    for (int s = 16; s > 0; s >>= 1) d += __shfl_xor_sync(0xffffffffu, d, s);
    if (lane == 0) wsum[w] = d;
    __syncthreads();
    if (t == 0) {
        float tot = (wsum[0] + wsum[1]) + (wsum[2] + wsum[3]);
        g_logits[k][u] = (tot / (float)deg) * g_xnorm[u];
    }
}

// ---------------- 8: npi softmax over nodes ----------------
__global__ __launch_bounds__(512) void k_npi(float* __restrict__ out_npi) {
    int k = blockIdx.x, t = threadIdx.x;
    __shared__ float red[512];
    float lv[4];
    float m = -1e30f;
    #pragma unroll
    for (int r = 0; r < 4; r++) { lv[r] = g_logits[k][t + r * 512]; m = fmaxf(m, lv[r]); }
    red[t] = m; __syncthreads();
    for (int s = 256; s > 0; s >>= 1) { if (t < s) red[t] = fmaxf(red[t], red[t + s]); __syncthreads(); }
    const float M = red[0]; __syncthreads();
    float ls = 0.f;
    #pragma unroll
    for (int r = 0; r < 4; r++) { lv[r] = expf(lv[r] - M); ls += lv[r]; }
    red[t] = ls; __syncthreads();
    for (int s = 256; s > 0; s >>= 1) { if (t < s) red[t] += red[t + s]; __syncthreads(); }
    const float invS = 1.f / red[0];
    #pragma unroll
    for (int r = 0; r < 4; r++)
        out_npi[(size_t)k * NN + t + r * 512] = lv[r] * invS;
}

// ---------------- launch (fork/join multi-stream graph) ----------------
static cudaStream_t g_s2 = nullptr;
static cudaEvent_t g_e0 = nullptr, g_e1 = nullptr, g_e2 = nullptr, g_e3 = nullptr;
static int g_multi = -1;

extern "C" void kernel_launch(void* const* d_in, const int* in_sizes, int n_in,
                              void* d_out, int out_size) {
    const float* H     = (const float*)d_in[0];
    const float* X     = (const float*)d_in[1];
    const int*   epoch = (const int*)  d_in[2];
    const float* w1    = (const float*)d_in[3];
    const float* b1    = (const float*)d_in[4];
    const float* w2    = (const float*)d_in[5];
    const float* b2    = (const float*)d_in[6];
    const float* compW = (const float*)d_in[7];
    const float* aw1   = (const float*)d_in[8];
    const float* ab1   = (const float*)d_in[9];
    const float* aw2   = (const float*)d_in[10];
    const float* ab2   = (const float*)d_in[11];
    float* out = (float*)d_out;

    const size_t OFF_G = (size_t)KK * NN * EE;
    const size_t OFF_E = OFF_G + KK;
    const size_t OFF_P = OFF_E + (size_t)KK * EE;

    cudaFuncSetAttribute(k_gemm, cudaFuncAttributeMaxDynamicSharedMemorySize, SM_BYTES);

    if (g_multi < 0) {
        bool ok = (cudaStreamCreateWithFlags(&g_s2, cudaStreamNonBlocking) == cudaSuccess)
               && (cudaEventCreateWithFlags(&g_e0, cudaEventDisableTiming) == cudaSuccess)
               && (cudaEventCreateWithFlags(&g_e1, cudaEventDisableTiming) == cudaSuccess)
               && (cudaEventCreateWithFlags(&g_e2, cudaEventDisableTiming) == cudaSuccess)
               && (cudaEventCreateWithFlags(&g_e3, cudaEventDisableTiming) == cudaSuccess);
        g_multi = ok ? 1 : 0;
    }

    if (g_multi == 1) {
        k_init<<<NN, 128>>>(X);
        cudaEventRecord(g_e0, 0);
        cudaStreamWaitEvent(g_s2, g_e0, 0);
        k_gemm<<<dim3(NN / GM, KK), 128, SM_BYTES, g_s2>>>(X, w1, b1, w2, b2, aw1, ab1, aw2, ab2);
        cudaEventRecord(g_e1, g_s2);
        k_edge<<<dim3(EE / 32, KK), 256>>>(H);
        cudaStreamWaitEvent(0, g_e1, 0);
        k_gateseg<<<KK + 1, 512>>>(compW, epoch, out + OFF_G, out + OFF_E);
        cudaEventRecord(g_e2, 0);
        cudaStreamWaitEvent(g_s2, g_e2, 0);
        k_adj<<<KK * EE / 8, 256, 0, g_s2>>>();
        k_nsum<<<dim3(NN, KK), 128, 0, g_s2>>>();
        k_npi<<<KK, 512, 0, g_s2>>>(out + OFF_P);
        cudaEventRecord(g_e3, g_s2);
        k_hp<<<dim3(EE / 128, NN / 64, KK), 256>>>(out);
        cudaStreamWaitEvent(0, g_e3, 0);
    } else {
        k_init<<<NN, 128>>>(X);
        k_edge<<<dim3(EE / 32, KK), 256>>>(H);
        k_gemm<<<dim3(NN / GM, KK), 128, SM_BYTES>>>(X, w1, b1, w2, b2, aw1, ab1, aw2, ab2);
        k_gateseg<<<KK + 1, 512>>>(compW, epoch, out + OFF_G, out + OFF_E);
        k_hp<<<dim3(EE / 128, NN / 64, KK), 256>>>(out);
        k_adj<<<KK * EE / 8, 256>>>();
        k_nsum<<<dim3(NN, KK), 128>>>();
        k_npi<<<KK, 512>>>(out + OFF_P);
    }
}

// round 6
// speedup vs baseline: 3.6000x; 1.0330x over previous
#include <cuda_runtime.h>
#include <cuda_fp16.h>
#include <cstdint>

#define KK 4
#define NN 2048
#define EE 4096
#define DD 128
#define NW 32
#define BETA  0.6f
#define EPSG  0.01f
#define LAMS  0.05f
#define TC0C  0.3f
#define TCMAXC 0.7f

typedef unsigned long long ull;

// ---------------- scratch (device globals; no allocation) ----------------
__device__ ull   g_colbits[KK][EE][NW];   // 4 MB
__device__ float g_imp[KK][EE];
__device__ float g_eg[KK][EE];
__device__ int   g_cnt[KK][EE];
__device__ float g_xhat[NN][DD];          // 1 MB
__device__ __half g_xhat_h[NN][DD];       // 0.5 MB (nsum gather)
__device__ float g_xnorm[NN];
__device__ float g_featn[KK];
__device__ float g_satt[KK];
__device__ float g_gates[KK];
__device__ float g_frobpart[64];
__device__ ull   g_adj[KK][NN][NN/64];    // 2 MB
__device__ float g_logits[KK][NN];

__device__ __forceinline__ float epoch_to_float(const int* p) {
    int ei = *p;
    return (ei >= 0 && ei < 1000000) ? (float)ei : __int_as_float(ei);
}

__device__ __forceinline__ ull pack2(float x) {
    ull r;
    unsigned u = __float_as_uint(x);
    asm("mov.b64 %0, {%1, %1};" : "=l"(r) : "r"(u));
    return r;
}
__device__ __forceinline__ void unpack2(ull v, float& lo, float& hi) {
    unsigned a, b;
    asm("mov.b64 {%0, %1}, %2;" : "=r"(a), "=r"(b) : "l"(v));
    lo = __uint_as_float(a); hi = __uint_as_float(b);
}
__device__ __forceinline__ void fma2(ull& acc, ull x, ull w) {
    asm("fma.rn.f32x2 %0, %1, %2, %0;" : "+l"(acc) : "l"(x), "l"(w));
}

// ---------------- 1: init (adj zero + xhat/xnorm/xhat_h + frob partials) ----------------
__global__ __launch_bounds__(128) void k_init(const float* __restrict__ X,
                                              const float* __restrict__ compW) {
    int n = blockIdx.x, t = threadIdx.x;
    ((ull*)g_adj)[(size_t)n * 128 + t] = 0ull;
    if (n == 0 && t < KK) { g_featn[t] = 0.f; g_satt[t] = 0.f; }
    __shared__ float red[128];
    float v = X[(size_t)n * DD + t];
    red[t] = v * v; __syncthreads();
    for (int s = 64; s > 0; s >>= 1) { if (t < s) red[t] += red[t + s]; __syncthreads(); }
    float norm = sqrtf(red[0]);
    float inv = 1.f / fmaxf(norm, 1e-8f);
    float xh = v * inv;
    g_xhat[n][t] = xh;
    g_xhat_h[n][t] = __float2half(xh);
    if (t == 0) g_xnorm[n] = norm;

    // frob partials: blocks 0..63 each reduce one 1024-float chunk of compW
    if (n < 64) {
        __syncthreads();
        const float* W = compW + (size_t)n * 1024;
        float s = 0.f;
        #pragma unroll
        for (int i = 0; i < 8; i++) { float w = W[t + i * 128]; s += w * w; }
        red[t] = s; __syncthreads();
        for (int st = 64; st > 0; st >>= 1) { if (t < st) red[t] += red[t + st]; __syncthreads(); }
        if (t == 0) g_frobpart[n] = red[0];
    }
}

// ---------------- 2: edge stats + bitsets + fused cosine importance ----------------
__global__ __launch_bounds__(256) void k_edge(const float* __restrict__ H) {
    const int k = blockIdx.y, et = blockIdx.x;     // et in [0, EE/32)
    const int t = threadIdx.x;
    const int eq = t & 7, oct = t >> 3;
    const int e0 = et * 32 + eq * 4;
    const float* base = H + ((size_t)k * NN + (size_t)oct * 64) * EE + e0;

    ull m0 = 0, m1 = 0, m2 = 0, m3 = 0;
    #pragma unroll 4
    for (int r = 0; r < 64; r++) {
        float4 v = *(const float4*)(base + (size_t)r * EE);
        ull bit = 1ull << r;
        if (v.x > 0.f) m0 |= bit;
        if (v.y > 0.f) m1 |= bit;
        if (v.z > 0.f) m2 |= bit;
        if (v.w > 0.f) m3 |= bit;
    }
    g_colbits[k][e0 + 0][oct] = m0;
    g_colbits[k][e0 + 1][oct] = m1;
    g_colbits[k][e0 + 2][oct] = m2;
    g_colbits[k][e0 + 3][oct] = m3;

    __shared__ short s_cnt[32][33];
    __shared__ short s_f[32][33];
    __shared__ short s_s[32][33];
    __shared__ int fi[32], fj[32], fc[32];

    {
        ull M[4] = {m0, m1, m2, m3};
        #pragma unroll
        for (int q = 0; q < 4; q++) {
            ull m = M[q];
            int c = __popcll(m);
            int f = c ? (oct * 64 + __ffsll((long long)m) - 1) : -1;
            int s2 = (c >= 2) ? (oct * 64 + __ffsll((long long)(m & (m - 1))) - 1) : -1;
            s_cnt[eq * 4 + q][oct] = (short)c;
            s_f[eq * 4 + q][oct]   = (short)f;
            s_s[eq * 4 + q][oct]   = (short)s2;
        }
    }
    __syncthreads();

    if (t < 32) {
        int e = et * 32 + t;
        int cnt = 0, i0 = 0, j0 = 0;
        #pragma unroll
        for (int o = 0; o < 32; o++) {
            int c = s_cnt[t][o];
            if (c > 0) {
                if (cnt == 0) { i0 = s_f[t][o]; if (c >= 2) j0 = s_s[t][o]; }
                else if (cnt == 1) { j0 = s_f[t][o]; }
                cnt += c;
            }
        }
        g_cnt[k][e] = cnt;
        fi[t] = i0; fj[t] = j0; fc[t] = cnt;
        g_imp[k][e] = (e < 500) ? ((cnt >= 2) ? 0.f : 0.1f) : 0.f;
    }
    __syncthreads();

    // fused cosine importance for scored edges (e < 500)
    if (et * 32 < 500) {
        int wl = t >> 5, lane = t & 31;
        for (int q = wl; q < 32; q += 8) {
            int e = et * 32 + q;
            if (e >= 500) continue;
            if (fc[q] < 2) continue;
            int i0 = fi[q], j0 = fj[q];
            float4 a = *(const float4*)&g_xhat[i0][lane * 4];
            float4 b = *(const float4*)&g_xhat[j0][lane * 4];
            float d = a.x * b.x + a.y * b.y + a.z * b.z + a.w * b.w;
            #pragma unroll
            for (int s = 16; s > 0; s >>= 1) d += __shfl_xor_sync(0xffffffffu, d, s);
            if (lane == 0) {
                const float* hb = H + (size_t)k * NN * EE + e;
                float A = hb[(size_t)i0 * EE] * hb[(size_t)j0 * EE];
                g_imp[k][e] = A * d;
            }
        }
    }
}

// ---------------- 3: component MLP + attention (f32x2 register tiles) ----------------
#define GM 32
#define XST 36
#define SM_BYTES ((4608 + 4608 + 4096) * 4)

__device__ __forceinline__ float layer128(const float* __restrict__ Xin,
                                          float* __restrict__ Ws,
                                          float* __restrict__ Xout,
                                          const float* __restrict__ Wg,
                                          const float* __restrict__ bg,
                                          bool relu, bool sq, int t)
{
    const int tr = t >> 4, tc = t & 15;
    const int r0 = tr * 4, o0 = tc * 8;
    ull acc2[4][4];
    #pragma unroll
    for (int a = 0; a < 4; a++)
        #pragma unroll
        for (int b = 0; b < 4; b++) acc2[a][b] = 0ull;

    for (int dc = 0; dc < 4; dc++) {
        __syncthreads();
        #pragma unroll
        for (int i = 0; i < 8; i++)
            ((float4*)Ws)[t + i * 128] = ((const float4*)Wg)[dc * 1024 + t + i * 128];
        __syncthreads();
        #pragma unroll 8
        for (int dl = 0; dl < 32; dl++) {
            int d = dc * 32 + dl;
            float4 xv = *(const float4*)&Xin[d * XST + r0];
            ull xb0 = pack2(xv.x), xb1 = pack2(xv.y), xb2 = pack2(xv.z), xb3 = pack2(xv.w);
            const ull* wrow = (const ull*)&Ws[dl * 128 + o0];
            ull w0 = wrow[0], w1 = wrow[1], w2 = wrow[2], w3 = wrow[3];
            fma2(acc2[0][0], xb0, w0); fma2(acc2[0][1], xb0, w1);
            fma2(acc2[0][2], xb0, w2); fma2(acc2[0][3], xb0, w3);
            fma2(acc2[1][0], xb1, w0); fma2(acc2[1][1], xb1, w1);
            fma2(acc2[1][2], xb1, w2); fma2(acc2[1][3], xb1, w3);
            fma2(acc2[2][0], xb2, w0); fma2(acc2[2][1], xb2, w1);
            fma2(acc2[2][2], xb2, w2); fma2(acc2[2][3], xb2, w3);
            fma2(acc2[3][0], xb3, w0); fma2(acc2[3][1], xb3, w1);
            fma2(acc2[3][2], xb3, w2); fma2(acc2[3][3], xb3, w3);
        }
    }
    __syncthreads();
    float fp = 0.f;
    #pragma unroll
    for (int rr = 0; rr < 4; rr++) {
        #pragma unroll
        for (int op = 0; op < 4; op++) {
            float lo, hi;
            unpack2(acc2[rr][op], lo, hi);
            float v0 = lo + bg[o0 + 2 * op];
            float v1 = hi + bg[o0 + 2 * op + 1];
            if (relu) { v0 = fmaxf(v0, 0.f); v1 = fmaxf(v1, 0.f); }
            if (sq) fp += v0 * v0 + v1 * v1;
            Xout[(o0 + 2 * op) * XST + r0 + rr]     = v0;
            Xout[(o0 + 2 * op + 1) * XST + r0 + rr] = v1;
        }
    }
    return fp;
}

__global__ __launch_bounds__(128) void k_gemm(
    const float* __restrict__ X,
    const float* __restrict__ w1, const float* __restrict__ b1,
    const float* __restrict__ w2, const float* __restrict__ b2,
    const float* __restrict__ aw1, const float* __restrict__ ab1,
    const float* __restrict__ aw2, const float* __restrict__ ab2)
{
    extern __shared__ float sm[];
    float* Xs = sm;
    float* Hs = sm + 4608;
    float* Ws = sm + 9216;
    float* As = Ws;
    float* red = Hs;

    const int k = blockIdx.y, nt = blockIdx.x, t = threadIdx.x;

    for (int idx = t; idx < 1024; idx += 128) {
        int row = idx >> 5, dq = idx & 31;
        float4 v = ((const float4*)X)[((size_t)(nt * GM + row)) * 32 + dq];
        Xs[(dq * 4 + 0) * XST + row] = v.x;
        Xs[(dq * 4 + 1) * XST + row] = v.y;
        Xs[(dq * 4 + 2) * XST + row] = v.z;
        Xs[(dq * 4 + 3) * XST + row] = v.w;
    }
    __syncthreads();

    layer128(Xs, Ws, Hs, w1 + (size_t)k * DD * DD, b1 + k * DD, true, false, t);
    __syncthreads();
    float fp = layer128(Hs, Ws, Xs, w2 + (size_t)k * DD * DD, b2 + k * DD, false, true, t);
    __syncthreads();

    const int tcA = t & 7, trA = t >> 3;
    const int oA = tcA * 8, rA = trA * 2;
    float aacc[2][8];
    #pragma unroll
    for (int a = 0; a < 2; a++)
        #pragma unroll
        for (int b = 0; b < 8; b++) aacc[a][b] = 0.f;
    const float* AWg = aw1 + (size_t)k * DD * 64;
    for (int dc = 0; dc < 4; dc++) {
        __syncthreads();
        #pragma unroll
        for (int i = 0; i < 4; i++)
            ((float4*)Ws)[t + i * 128] = ((const float4*)AWg)[dc * 512 + t + i * 128];
        __syncthreads();
        #pragma unroll 8
        for (int dl = 0; dl < 32; dl++) {
            int d = dc * 32 + dl;
            float2 xv = *(const float2*)&Xs[d * XST + rA];
            float4 w0 = *(const float4*)&Ws[dl * 64 + oA];
            float4 w1v = *(const float4*)&Ws[dl * 64 + oA + 4];
            aacc[0][0] += xv.x * w0.x;  aacc[0][1] += xv.x * w0.y;
            aacc[0][2] += xv.x * w0.z;  aacc[0][3] += xv.x * w0.w;
            aacc[0][4] += xv.x * w1v.x; aacc[0][5] += xv.x * w1v.y;
            aacc[0][6] += xv.x * w1v.z; aacc[0][7] += xv.x * w1v.w;
            aacc[1][0] += xv.y * w0.x;  aacc[1][1] += xv.y * w0.y;
            aacc[1][2] += xv.y * w0.z;  aacc[1][3] += xv.y * w0.w;
            aacc[1][4] += xv.y * w1v.x; aacc[1][5] += xv.y * w1v.y;
            aacc[1][6] += xv.y * w1v.z; aacc[1][7] += xv.y * w1v.w;
        }
    }
    __syncthreads();
    #pragma unroll
    for (int rr = 0; rr < 2; rr++)
        #pragma unroll
        for (int oo = 0; oo < 8; oo++)
            As[(oA + oo) * 33 + rA + rr] = fmaxf(aacc[rr][oo] + ab1[k * 64 + oA + oo], 0.f);
    __syncthreads();

    float sattp = 0.f;
    if (t < GM) {
        float s = ab2[k];
        const float* AW2 = aw2 + (size_t)k * 64;
        #pragma unroll 8
        for (int h = 0; h < 64; h++) s += As[h * 33 + t] * AW2[h];
        sattp = 1.f / (1.f + expf(-s));
    }

    __syncthreads();
    red[t] = fp; __syncthreads();
    for (int s = 64; s > 0; s >>= 1) { if (t < s) red[t] += red[t + s]; __syncthreads(); }
    if (t == 0) atomicAdd(&g_featn[k], red[0]);
    __syncthreads();
    red[t] = sattp; __syncthreads();
    for (int s = 64; s > 0; s >>= 1) { if (t < s) red[t] += red[t + s]; __syncthreads(); }
    if (t == 0) atomicAdd(&g_satt[k], red[0]);
}

// ---------------- 4: gates (block 0) + edge softmax/eg (blocks 1..K) ----------------
__global__ __launch_bounds__(512) void k_gateseg(
    const int* __restrict__ epochp,
    float* __restrict__ out_gates, float* __restrict__ out_eg)
{
    const int t = threadIdx.x, lane = t & 31, wid = t >> 5;
    __shared__ float sm[16];
    __shared__ int smi[16];

    if (blockIdx.x == 0) {
        // fold 64 frob partials: t<64, group of 16 per k
        if (t < 64) {
            float v = g_frobpart[t];
            #pragma unroll
            for (int d = 8; d > 0; d >>= 1) v += __shfl_xor_sync(0xffffffffu, v, d);
            if ((t & 15) == 0) sm[t >> 4] = v;
        }
        __syncthreads();
        if (t == 0) {
            float ep = epoch_to_float(epochp);
            float theta_c = TC0C + (1.f - expf(-LAMS * ep)) * (TCMAXC - TC0C);
            float imp[KK], pi[KK], g[KK];
            float m = -1e30f;
            for (int k2 = 0; k2 < KK; k2++) {
                float fr = sqrtf(sm[k2]);
                imp[k2] = BETA * fr * sqrtf(g_featn[k2]) + (1.f - BETA) * (g_satt[k2] / (float)NN);
                m = fmaxf(m, imp[k2]);
            }
            float su = 0.f;
            for (int k2 = 0; k2 < KK; k2++) { pi[k2] = expf(imp[k2] - m); su += pi[k2]; }
            float gmax = -1.f; int am = 0;
            for (int k2 = 0; k2 < KK; k2++) {
                pi[k2] /= su;
                g[k2] = fminf(fmaxf((pi[k2] - theta_c) / EPSG + 0.5f, 0.f), 1.f);
                if (g[k2] > gmax) { gmax = g[k2]; am = k2; }
            }
            g[am] = fmaxf(g[am], 1.f);
            for (int k2 = 0; k2 < KK; k2++) { g_gates[k2] = g[k2]; out_gates[k2] = g[k2]; }
        }
        return;
    }

    const int k = blockIdx.x - 1;
    float lv[8];

    // final butterfly covers sm[0..15] exactly once (xor distances 8..1 stay
    // within a 16-lane group) — no correction factor.
    auto redsum = [&](float v) -> float {
        __syncthreads();
        #pragma unroll
        for (int d = 16; d > 0; d >>= 1) v += __shfl_xor_sync(0xffffffffu, v, d);
        if (lane == 0) sm[wid] = v;
        __syncthreads();
        if (wid == 0) {
            float x = sm[lane & 15];
            #pragma unroll
            for (int d = 8; d > 0; d >>= 1) x += __shfl_xor_sync(0xffffffffu, x, d);
            if (lane == 0) sm[0] = x;
        }
        __syncthreads();
        return sm[0];
    };
    auto redmax = [&](float v) -> float {
        __syncthreads();
        #pragma unroll
        for (int d = 16; d > 0; d >>= 1) v = fmaxf(v, __shfl_xor_sync(0xffffffffu, v, d));
        if (lane == 0) sm[wid] = v;
        __syncthreads();
        if (wid == 0) {
            float x = sm[lane & 15];
            #pragma unroll
            for (int d = 8; d > 0; d >>= 1) x = fmaxf(x, __shfl_xor_sync(0xffffffffu, x, d));
            if (lane == 0) sm[0] = x;
        }
        __syncthreads();
        return sm[0];
    };
    auto redargmax = [&](float v, int i) -> int {
        __syncthreads();
        #pragma unroll
        for (int d = 16; d > 0; d >>= 1) {
            float ov = __shfl_xor_sync(0xffffffffu, v, d);
            int   oi = __shfl_xor_sync(0xffffffffu, i, d);
            if (ov > v || (ov == v && oi < i)) { v = ov; i = oi; }
        }
        if (lane == 0) { sm[wid] = v; smi[wid] = i; }
        __syncthreads();
        if (wid == 0) {
            float x = sm[lane & 15]; int xi = smi[lane & 15];
            #pragma unroll
            for (int d = 8; d > 0; d >>= 1) {
                float ov = __shfl_xor_sync(0xffffffffu, x, d);
                int   oi = __shfl_xor_sync(0xffffffffu, xi, d);
                if (ov > x || (ov == x && oi < xi)) { x = ov; xi = oi; }
            }
            if (lane == 0) smi[0] = xi;
        }
        __syncthreads();
        return smi[0];
    };

    float vmax = -1e30f;
    #pragma unroll
    for (int r = 0; r < 8; r++) { lv[r] = g_imp[k][t + r * 512]; vmax = fmaxf(vmax, lv[r]); }
    const float M = redmax(vmax);

    float lsum = 0.f;
    #pragma unroll
    for (int r = 0; r < 8; r++) { lv[r] = expf(lv[r] - M); lsum += lv[r]; }
    const float invS = 1.f / redsum(lsum);

    float tsum = 0.f;
    #pragma unroll
    for (int r = 0; r < 8; r++) { lv[r] *= invS; tsum += lv[r]; }
    const float mean = redsum(tsum) / (float)EE;

    float lvar = 0.f;
    #pragma unroll
    for (int r = 0; r < 8; r++) { float d = lv[r] - mean; lvar += d * d; }
    const float stdv = sqrtf(redsum(lvar) / (float)(EE - 1));

    float ep = epoch_to_float(epochp);
    float theta_c = TC0C + (1.f - expf(-LAMS * ep)) * (TCMAXC - TC0C);
    float theta = fminf(theta_c, mean + stdv);

    float seg = 0.f, pmax = -1e30f; int pam = EE;
    float le[8];
    #pragma unroll
    for (int r = 0; r < 8; r++) {
        int idx = t + r * 512;
        float p = lv[r];
        float e_g = fminf(fmaxf((p - theta) / EPSG + 0.5f, 0.f), 1.f);
        le[r] = e_g; seg += e_g;
        if (p > pmax) { pmax = p; pam = idx; }
    }
    const float sumEg = redsum(seg);
    const int am = redargmax(pmax, pam);

    #pragma unroll
    for (int r = 0; r < 8; r++) {
        int idx = t + r * 512;
        float v = le[r];
        if (sumEg < 1.f && idx == am) v = 1.f;
        g_eg[k][idx] = v;
        out_eg[(size_t)k * EE + idx] = v;
    }
}

// ---------------- 5: write Hp from bitsets (hval inlined) ----------------
__global__ __launch_bounds__(256) void k_hp(float* __restrict__ out) {
    int k = blockIdx.z, nt = blockIdx.y, et = blockIdx.x;
    int t = threadIdx.x;
    __shared__ ull bw[128];
    __shared__ float hv[128];
    if (t < 128) {
        int e = et * 128 + t;
        float g = g_gates[k];
        float eg = g_eg[k][e];
        hv[t] = g * (g > 0.5f ? eg : 1.f);
        bw[t] = g_colbits[k][e][nt];
    }
    __syncthreads();
    #pragma unroll
    for (int r = 0; r < 8; r++) {
        int idx = t + r * 256;
        int nl = idx >> 5, q = idx & 31, el = q * 4;
        float4 v;
        v.x = ((bw[el + 0] >> nl) & 1ull) ? hv[el + 0] : 0.f;
        v.y = ((bw[el + 1] >> nl) & 1ull) ? hv[el + 1] : 0.f;
        v.z = ((bw[el + 2] >> nl) & 1ull) ? hv[el + 2] : 0.f;
        v.w = ((bw[el + 3] >> nl) & 1ull) ? hv[el + 3] : 0.f;
        *(float4*)&out[((size_t)k * NN + (size_t)nt * 64 + nl) * EE + et * 128 + el] = v;
    }
}

// ---------------- 6: sparse adjacency build (warp per edge) ----------------
__global__ __launch_bounds__(256) void k_adj() {
    int wId = (blockIdx.x * blockDim.x + threadIdx.x) >> 5;
    int lane = threadIdx.x & 31;
    int wl = threadIdx.x >> 5;
    int k = wId / EE, e = wId % EE;
    __shared__ unsigned short list[8][1024];
    __shared__ int scnt[8];
    float g = g_gates[k];
    if (g <= 0.f) return;
    if (g > 0.5f && g_eg[k][e] <= 0.f) return;
    if (g_cnt[k][e] < 2) return;
    if (lane == 0) scnt[wl] = 0;
    __syncwarp();
    ull m = g_colbits[k][e][lane];
    while (m) {
        int b = __ffsll((long long)m) - 1;
        m &= m - 1;
        int pos = atomicAdd(&scnt[wl], 1);
        if (pos < 1024) list[wl][pos] = (unsigned short)(lane * 64 + b);
    }
    __syncwarp();
    int cN = scnt[wl];
    if (cN > 1024) cN = 1024;
    for (int p = lane; p < cN * cN; p += 32) {
        int u = list[wl][p / cN];
        int v = list[wl][p % cN];
        if (u != v)
            atomicOr(&g_adj[k][u][v >> 6], 1ull << (v & 63));
    }
}

// ---------------- 7: neighbor sum -> logits (4 warps, half2 rows) ----------------
__global__ __launch_bounds__(128) void k_nsum() {
    int u = blockIdx.x, k = blockIdx.y, t = threadIdx.x;
    int w = t >> 5, lane = t & 31;
    __shared__ unsigned short list[NN];
    __shared__ int s_deg;
    __shared__ float wsum[4];
    if (t < 32) {
        ull m = g_adj[k][u][t];
        int c = __popcll(m);
        int off = c;
        #pragma unroll
        for (int d = 1; d < 32; d <<= 1) {
            int x = __shfl_up_sync(0xffffffffu, off, d);
            if (t >= d) off += x;
        }
        off -= c;
        int pos = off;
        while (m) {
            int b = __ffsll((long long)m) - 1;
            m &= m - 1;
            list[pos++] = (unsigned short)(t * 64 + b);
        }
        if (t == 31) s_deg = off + c;
    }
    __syncthreads();
    int deg = s_deg;
    if (deg == 0) {
        if (t == 0) g_logits[k][u] = 0.f;
        return;
    }
    float4 acc = make_float4(0.f, 0.f, 0.f, 0.f);
    for (int i = w; i < deg; i += 4) {
        int v = list[i];
        const __half2* row = (const __half2*)&g_xhat_h[v][lane * 4];
        float2 a = __half22float2(row[0]);
        float2 b = __half22float2(row[1]);
        acc.x += a.x; acc.y += a.y; acc.z += b.x; acc.w += b.y;
    }
    float4 uf = *(const float4*)&g_xhat[u][lane * 4];
    float d = acc.x * uf.x + acc.y * uf.y + acc.z * uf.z + acc.w * uf.w;
    #pragma unroll
    for (int s = 16; s > 0; s >>= 1) d += __shfl_xor_sync(0xffffffffu, d, s);
    if (lane == 0) wsum[w] = d;
    __syncthreads();
    if (t == 0) {
        float tot = (wsum[0] + wsum[1]) + (wsum[2] + wsum[3]);
        g_logits[k][u] = (tot / (float)deg) * g_xnorm[u];
    }
}

// ---------------- 8: npi softmax over nodes ----------------
__global__ __launch_bounds__(512) void k_npi(float* __restrict__ out_npi) {
    int k = blockIdx.x, t = threadIdx.x;
    __shared__ float red[512];
    float lv[4];
    float m = -1e30f;
    #pragma unroll
    for (int r = 0; r < 4; r++) { lv[r] = g_logits[k][t + r * 512]; m = fmaxf(m, lv[r]); }
    red[t] = m; __syncthreads();
    for (int s = 256; s > 0; s >>= 1) { if (t < s) red[t] = fmaxf(red[t], red[t + s]); __syncthreads(); }
    const float M = red[0]; __syncthreads();
    float ls = 0.f;
    #pragma unroll
    for (int r = 0; r < 4; r++) { lv[r] = expf(lv[r] - M); ls += lv[r]; }
    red[t] = ls; __syncthreads();
    for (int s = 256; s > 0; s >>= 1) { if (t < s) red[t] += red[t + s]; __syncthreads(); }
    const float invS = 1.f / red[0];
    #pragma unroll
    for (int r = 0; r < 4; r++)
        out_npi[(size_t)k * NN + t + r * 512] = lv[r] * invS;
}

// ---------------- launch (fork/join multi-stream graph) ----------------
static cudaStream_t g_s2 = nullptr;
static cudaEvent_t g_e0 = nullptr, g_e1 = nullptr, g_e2 = nullptr, g_e3 = nullptr;
static int g_multi = -1;

extern "C" void kernel_launch(void* const* d_in, const int* in_sizes, int n_in,
                              void* d_out, int out_size) {
    const float* H     = (const float*)d_in[0];
    const float* X     = (const float*)d_in[1];
    const int*   epoch = (const int*)  d_in[2];
    const float* w1    = (const float*)d_in[3];
    const float* b1    = (const float*)d_in[4];
    const float* w2    = (const float*)d_in[5];
    const float* b2    = (const float*)d_in[6];
    const float* compW = (const float*)d_in[7];
    const float* aw1   = (const float*)d_in[8];
    const float* ab1   = (const float*)d_in[9];
    const float* aw2   = (const float*)d_in[10];
    const float* ab2   = (const float*)d_in[11];
    float* out = (float*)d_out;

    const size_t OFF_G = (size_t)KK * NN * EE;
    const size_t OFF_E = OFF_G + KK;
    const size_t OFF_P = OFF_E + (size_t)KK * EE;

    cudaFuncSetAttribute(k_gemm, cudaFuncAttributeMaxDynamicSharedMemorySize, SM_BYTES);

    if (g_multi < 0) {
        bool ok = (cudaStreamCreateWithFlags(&g_s2, cudaStreamNonBlocking) == cudaSuccess)
               && (cudaEventCreateWithFlags(&g_e0, cudaEventDisableTiming) == cudaSuccess)
               && (cudaEventCreateWithFlags(&g_e1, cudaEventDisableTiming) == cudaSuccess)
               && (cudaEventCreateWithFlags(&g_e2, cudaEventDisableTiming) == cudaSuccess)
               && (cudaEventCreateWithFlags(&g_e3, cudaEventDisableTiming) == cudaSuccess);
        g_multi = ok ? 1 : 0;
    }

    if (g_multi == 1) {
        k_init<<<NN, 128>>>(X, compW);
        cudaEventRecord(g_e0, 0);
        cudaStreamWaitEvent(g_s2, g_e0, 0);
        k_gemm<<<dim3(NN / GM, KK), 128, SM_BYTES, g_s2>>>(X, w1, b1, w2, b2, aw1, ab1, aw2, ab2);
        cudaEventRecord(g_e1, g_s2);
        k_edge<<<dim3(EE / 32, KK), 256>>>(H);
        cudaStreamWaitEvent(0, g_e1, 0);
        k_gateseg<<<KK + 1, 512>>>(epoch, out + OFF_G, out + OFF_E);
        cudaEventRecord(g_e2, 0);
        cudaStreamWaitEvent(g_s2, g_e2, 0);
        k_adj<<<KK * EE / 8, 256, 0, g_s2>>>();
        k_nsum<<<dim3(NN, KK), 128, 0, g_s2>>>();
        k_npi<<<KK, 512, 0, g_s2>>>(out + OFF_P);
        cudaEventRecord(g_e3, g_s2);
        k_hp<<<dim3(EE / 128, NN / 64, KK), 256>>>(out);
        cudaStreamWaitEvent(0, g_e3, 0);
    } else {
        k_init<<<NN, 128>>>(X, compW);
        k_edge<<<dim3(EE / 32, KK), 256>>>(H);
        k_gemm<<<dim3(NN / GM, KK), 128, SM_BYTES>>>(X, w1, b1, w2, b2, aw1, ab1, aw2, ab2);
        k_gateseg<<<KK + 1, 512>>>(epoch, out + OFF_G, out + OFF_E);
        k_hp<<<dim3(EE / 128, NN / 64, KK), 256>>>(out);
        k_adj<<<KK * EE / 8, 256>>>();
        k_nsum<<<dim3(NN, KK), 128>>>();
        k_npi<<<KK, 512>>>(out + OFF_P);
    }
}

// round 7
// speedup vs baseline: 3.6130x; 1.0036x over previous
#include <cuda_runtime.h>
#include <cuda_fp16.h>
#include <cstdint>

#define KK 4
#define NN 2048
#define EE 4096
#define DD 128
#define NW 32
#define BETA  0.6f
#define EPSG  0.01f
#define LAMS  0.05f
#define TC0C  0.3f
#define TCMAXC 0.7f

typedef unsigned long long ull;

// ---------------- scratch (device globals; no allocation) ----------------
__device__ ull   g_colbits[KK][EE][NW];   // 4 MB
__device__ float g_imp[KK][EE];
__device__ float g_eg[KK][EE];
__device__ int   g_cnt[KK][EE];
__device__ float g_xhat[NN][DD];          // 1 MB
__device__ __half g_xhat_h[NN][DD];       // 0.5 MB (nsum gather)
__device__ float g_xnorm[NN];
__device__ float g_featn[KK];
__device__ float g_satt[KK];
__device__ float g_gates[KK];
__device__ float g_frobpart[64];
__device__ ull   g_adj[KK][NN][NN/64];    // 2 MB
__device__ float g_logits[KK][NN];

__device__ __forceinline__ float epoch_to_float(const int* p) {
    int ei = *p;
    return (ei >= 0 && ei < 1000000) ? (float)ei : __int_as_float(ei);
}

__device__ __forceinline__ ull pack2(float x) {
    ull r;
    unsigned u = __float_as_uint(x);
    asm("mov.b64 %0, {%1, %1};" : "=l"(r) : "r"(u));
    return r;
}
__device__ __forceinline__ void unpack2(ull v, float& lo, float& hi) {
    unsigned a, b;
    asm("mov.b64 {%0, %1}, %2;" : "=r"(a), "=r"(b) : "l"(v));
    lo = __uint_as_float(a); hi = __uint_as_float(b);
}
__device__ __forceinline__ void fma2(ull& acc, ull x, ull w) {
    asm("fma.rn.f32x2 %0, %1, %2, %0;" : "+l"(acc) : "l"(x), "l"(w));
}

// ---------------- 1: init (adj zero + xhat/xnorm/xhat_h + frob partials) ----------------
__global__ __launch_bounds__(128) void k_init(const float* __restrict__ X,
                                              const float* __restrict__ compW) {
    int n = blockIdx.x, t = threadIdx.x;
    ((ull*)g_adj)[(size_t)n * 128 + t] = 0ull;
    if (n == 0 && t < KK) { g_featn[t] = 0.f; g_satt[t] = 0.f; }
    __shared__ float red[128];
    float v = X[(size_t)n * DD + t];
    red[t] = v * v; __syncthreads();
    for (int s = 64; s > 0; s >>= 1) { if (t < s) red[t] += red[t + s]; __syncthreads(); }
    float norm = sqrtf(red[0]);
    float inv = 1.f / fmaxf(norm, 1e-8f);
    float xh = v * inv;
    g_xhat[n][t] = xh;
    g_xhat_h[n][t] = __float2half(xh);
    if (t == 0) g_xnorm[n] = norm;

    if (n < 64) {
        __syncthreads();
        const float* W = compW + (size_t)n * 1024;
        float s = 0.f;
        #pragma unroll
        for (int i = 0; i < 8; i++) { float w = W[t + i * 128]; s += w * w; }
        red[t] = s; __syncthreads();
        for (int st = 64; st > 0; st >>= 1) { if (t < st) red[t] += red[t + st]; __syncthreads(); }
        if (t == 0) g_frobpart[n] = red[0];
    }
}

// ---------------- 2: edge stats + bitsets + fused cosine importance ----------------
__global__ __launch_bounds__(256) void k_edge(const float* __restrict__ H) {
    const int k = blockIdx.y, et = blockIdx.x;     // et in [0, EE/32)
    const int t = threadIdx.x;
    const int eq = t & 7, oct = t >> 3;
    const int e0 = et * 32 + eq * 4;
    const float* base = H + ((size_t)k * NN + (size_t)oct * 64) * EE + e0;

    ull m0 = 0, m1 = 0, m2 = 0, m3 = 0;
    #pragma unroll 4
    for (int r = 0; r < 64; r++) {
        float4 v = *(const float4*)(base + (size_t)r * EE);
        ull bit = 1ull << r;
        if (v.x > 0.f) m0 |= bit;
        if (v.y > 0.f) m1 |= bit;
        if (v.z > 0.f) m2 |= bit;
        if (v.w > 0.f) m3 |= bit;
    }
    g_colbits[k][e0 + 0][oct] = m0;
    g_colbits[k][e0 + 1][oct] = m1;
    g_colbits[k][e0 + 2][oct] = m2;
    g_colbits[k][e0 + 3][oct] = m3;

    __shared__ short s_cnt[32][33];
    __shared__ short s_f[32][33];
    __shared__ short s_s[32][33];
    __shared__ int fi[32], fj[32], fc[32];

    {
        ull M[4] = {m0, m1, m2, m3};
        #pragma unroll
        for (int q = 0; q < 4; q++) {
            ull m = M[q];
            int c = __popcll(m);
            int f = c ? (oct * 64 + __ffsll((long long)m) - 1) : -1;
            int s2 = (c >= 2) ? (oct * 64 + __ffsll((long long)(m & (m - 1))) - 1) : -1;
            s_cnt[eq * 4 + q][oct] = (short)c;
            s_f[eq * 4 + q][oct]   = (short)f;
            s_s[eq * 4 + q][oct]   = (short)s2;
        }
    }
    __syncthreads();

    if (t < 32) {
        int e = et * 32 + t;
        int cnt = 0, i0 = 0, j0 = 0;
        #pragma unroll
        for (int o = 0; o < 32; o++) {
            int c = s_cnt[t][o];
            if (c > 0) {
                if (cnt == 0) { i0 = s_f[t][o]; if (c >= 2) j0 = s_s[t][o]; }
                else if (cnt == 1) { j0 = s_f[t][o]; }
                cnt += c;
            }
        }
        g_cnt[k][e] = cnt;
        fi[t] = i0; fj[t] = j0; fc[t] = cnt;
        g_imp[k][e] = (e < 500) ? ((cnt >= 2) ? 0.f : 0.1f) : 0.f;
    }
    __syncthreads();

    if (et * 32 < 500) {
        int wl = t >> 5, lane = t & 31;
        for (int q = wl; q < 32; q += 8) {
            int e = et * 32 + q;
            if (e >= 500) continue;
            if (fc[q] < 2) continue;
            int i0 = fi[q], j0 = fj[q];
            float4 a = *(const float4*)&g_xhat[i0][lane * 4];
            float4 b = *(const float4*)&g_xhat[j0][lane * 4];
            float d = a.x * b.x + a.y * b.y + a.z * b.z + a.w * b.w;
            #pragma unroll
            for (int s = 16; s > 0; s >>= 1) d += __shfl_xor_sync(0xffffffffu, d, s);
            if (lane == 0) {
                const float* hb = H + (size_t)k * NN * EE + e;
                float A = hb[(size_t)i0 * EE] * hb[(size_t)j0 * EE];
                g_imp[k][e] = A * d;
            }
        }
    }
}

// ---------------- 3: component MLP + attention (f32x2 register tiles) ----------------
#define GM 32
#define XST 36
#define SM_BYTES ((4608 + 4608 + 4096) * 4)

__device__ __forceinline__ float layer128(const float* __restrict__ Xin,
                                          float* __restrict__ Ws,
                                          float* __restrict__ Xout,
                                          const float* __restrict__ Wg,
                                          const float* __restrict__ bg,
                                          bool relu, bool sq, int t)
{
    const int tr = t >> 4, tc = t & 15;
    const int r0 = tr * 4, o0 = tc * 8;
    ull acc2[4][4];
    #pragma unroll
    for (int a = 0; a < 4; a++)
        #pragma unroll
        for (int b = 0; b < 4; b++) acc2[a][b] = 0ull;

    for (int dc = 0; dc < 4; dc++) {
        __syncthreads();
        #pragma unroll
        for (int i = 0; i < 8; i++)
            ((float4*)Ws)[t + i * 128] = ((const float4*)Wg)[dc * 1024 + t + i * 128];
        __syncthreads();
        #pragma unroll 8
        for (int dl = 0; dl < 32; dl++) {
            int d = dc * 32 + dl;
            float4 xv = *(const float4*)&Xin[d * XST + r0];
            ull xb0 = pack2(xv.x), xb1 = pack2(xv.y), xb2 = pack2(xv.z), xb3 = pack2(xv.w);
            const ull* wrow = (const ull*)&Ws[dl * 128 + o0];
            ull w0 = wrow[0], w1 = wrow[1], w2 = wrow[2], w3 = wrow[3];
            fma2(acc2[0][0], xb0, w0); fma2(acc2[0][1], xb0, w1);
            fma2(acc2[0][2], xb0, w2); fma2(acc2[0][3], xb0, w3);
            fma2(acc2[1][0], xb1, w0); fma2(acc2[1][1], xb1, w1);
            fma2(acc2[1][2], xb1, w2); fma2(acc2[1][3], xb1, w3);
            fma2(acc2[2][0], xb2, w0); fma2(acc2[2][1], xb2, w1);
            fma2(acc2[2][2], xb2, w2); fma2(acc2[2][3], xb2, w3);
            fma2(acc2[3][0], xb3, w0); fma2(acc2[3][1], xb3, w1);
            fma2(acc2[3][2], xb3, w2); fma2(acc2[3][3], xb3, w3);
        }
    }
    __syncthreads();
    float fp = 0.f;
    #pragma unroll
    for (int rr = 0; rr < 4; rr++) {
        #pragma unroll
        for (int op = 0; op < 4; op++) {
            float lo, hi;
            unpack2(acc2[rr][op], lo, hi);
            float v0 = lo + bg[o0 + 2 * op];
            float v1 = hi + bg[o0 + 2 * op + 1];
            if (relu) { v0 = fmaxf(v0, 0.f); v1 = fmaxf(v1, 0.f); }
            if (sq) fp += v0 * v0 + v1 * v1;
            Xout[(o0 + 2 * op) * XST + r0 + rr]     = v0;
            Xout[(o0 + 2 * op + 1) * XST + r0 + rr] = v1;
        }
    }
    return fp;
}

__global__ __launch_bounds__(128) void k_gemm(
    const float* __restrict__ X,
    const float* __restrict__ w1, const float* __restrict__ b1,
    const float* __restrict__ w2, const float* __restrict__ b2,
    const float* __restrict__ aw1, const float* __restrict__ ab1,
    const float* __restrict__ aw2, const float* __restrict__ ab2)
{
    extern __shared__ float sm[];
    float* Xs = sm;
    float* Hs = sm + 4608;
    float* Ws = sm + 9216;
    float* As = Ws;
    float* red = Hs;

    const int k = blockIdx.y, nt = blockIdx.x, t = threadIdx.x;

    for (int idx = t; idx < 1024; idx += 128) {
        int row = idx >> 5, dq = idx & 31;
        float4 v = ((const float4*)X)[((size_t)(nt * GM + row)) * 32 + dq];
        Xs[(dq * 4 + 0) * XST + row] = v.x;
        Xs[(dq * 4 + 1) * XST + row] = v.y;
        Xs[(dq * 4 + 2) * XST + row] = v.z;
        Xs[(dq * 4 + 3) * XST + row] = v.w;
    }
    __syncthreads();

    layer128(Xs, Ws, Hs, w1 + (size_t)k * DD * DD, b1 + k * DD, true, false, t);
    __syncthreads();
    float fp = layer128(Hs, Ws, Xs, w2 + (size_t)k * DD * DD, b2 + k * DD, false, true, t);
    __syncthreads();

    const int tcA = t & 7, trA = t >> 3;
    const int oA = tcA * 8, rA = trA * 2;
    float aacc[2][8];
    #pragma unroll
    for (int a = 0; a < 2; a++)
        #pragma unroll
        for (int b = 0; b < 8; b++) aacc[a][b] = 0.f;
    const float* AWg = aw1 + (size_t)k * DD * 64;
    for (int dc = 0; dc < 4; dc++) {
        __syncthreads();
        #pragma unroll
        for (int i = 0; i < 4; i++)
            ((float4*)Ws)[t + i * 128] = ((const float4*)AWg)[dc * 512 + t + i * 128];
        __syncthreads();
        #pragma unroll 8
        for (int dl = 0; dl < 32; dl++) {
            int d = dc * 32 + dl;
            float2 xv = *(const float2*)&Xs[d * XST + rA];
            float4 w0 = *(const float4*)&Ws[dl * 64 + oA];
            float4 w1v = *(const float4*)&Ws[dl * 64 + oA + 4];
            aacc[0][0] += xv.x * w0.x;  aacc[0][1] += xv.x * w0.y;
            aacc[0][2] += xv.x * w0.z;  aacc[0][3] += xv.x * w0.w;
            aacc[0][4] += xv.x * w1v.x; aacc[0][5] += xv.x * w1v.y;
            aacc[0][6] += xv.x * w1v.z; aacc[0][7] += xv.x * w1v.w;
            aacc[1][0] += xv.y * w0.x;  aacc[1][1] += xv.y * w0.y;
            aacc[1][2] += xv.y * w0.z;  aacc[1][3] += xv.y * w0.w;
            aacc[1][4] += xv.y * w1v.x; aacc[1][5] += xv.y * w1v.y;
            aacc[1][6] += xv.y * w1v.z; aacc[1][7] += xv.y * w1v.w;
        }
    }
    __syncthreads();
    #pragma unroll
    for (int rr = 0; rr < 2; rr++)
        #pragma unroll
        for (int oo = 0; oo < 8; oo++)
            As[(oA + oo) * 33 + rA + rr] = fmaxf(aacc[rr][oo] + ab1[k * 64 + oA + oo], 0.f);
    __syncthreads();

    float sattp = 0.f;
    if (t < GM) {
        float s = ab2[k];
        const float* AW2 = aw2 + (size_t)k * 64;
        #pragma unroll 8
        for (int h = 0; h < 64; h++) s += As[h * 33 + t] * AW2[h];
        sattp = 1.f / (1.f + expf(-s));
    }

    __syncthreads();
    red[t] = fp; __syncthreads();
    for (int s = 64; s > 0; s >>= 1) { if (t < s) red[t] += red[t + s]; __syncthreads(); }
    if (t == 0) atomicAdd(&g_featn[k], red[0]);
    __syncthreads();
    red[t] = sattp; __syncthreads();
    for (int s = 64; s > 0; s >>= 1) { if (t < s) red[t] += red[t + s]; __syncthreads(); }
    if (t == 0) atomicAdd(&g_satt[k], red[0]);
}

// ---------------- 4a: component gates (tiny; needs only gemm outputs) ----------------
__global__ void k_gates(const int* __restrict__ epochp, float* __restrict__ out_gates) {
    int t = threadIdx.x;   // 64 threads
    __shared__ float sm[4];
    float v = g_frobpart[t];
    #pragma unroll
    for (int d = 8; d > 0; d >>= 1) v += __shfl_xor_sync(0xffffffffu, v, d);
    if ((t & 15) == 0) sm[t >> 4] = v;
    __syncthreads();
    if (t == 0) {
        float ep = epoch_to_float(epochp);
        float theta_c = TC0C + (1.f - expf(-LAMS * ep)) * (TCMAXC - TC0C);
        float imp[KK], pi[KK], g[KK];
        float m = -1e30f;
        for (int k2 = 0; k2 < KK; k2++) {
            float fr = sqrtf(sm[k2]);
            imp[k2] = BETA * fr * sqrtf(g_featn[k2]) + (1.f - BETA) * (g_satt[k2] / (float)NN);
            m = fmaxf(m, imp[k2]);
        }
        float su = 0.f;
        for (int k2 = 0; k2 < KK; k2++) { pi[k2] = expf(imp[k2] - m); su += pi[k2]; }
        float gmax = -1.f; int am = 0;
        for (int k2 = 0; k2 < KK; k2++) {
            pi[k2] /= su;
            g[k2] = fminf(fmaxf((pi[k2] - theta_c) / EPSG + 0.5f, 0.f), 1.f);
            if (g[k2] > gmax) { gmax = g[k2]; am = k2; }
        }
        g[am] = fmaxf(g[am], 1.f);
        for (int k2 = 0; k2 < KK; k2++) { g_gates[k2] = g[k2]; out_gates[k2] = g[k2]; }
    }
}

// ---------------- 4b: edge softmax / eg ----------------
__global__ __launch_bounds__(512) void k_eg(const int* __restrict__ epochp,
                                            float* __restrict__ out_eg)
{
    const int t = threadIdx.x, lane = t & 31, wid = t >> 5;
    const int k = blockIdx.x;
    __shared__ float sm[16];
    __shared__ int smi[16];
    float lv[8];

    auto redsum = [&](float v) -> float {
        __syncthreads();
        #pragma unroll
        for (int d = 16; d > 0; d >>= 1) v += __shfl_xor_sync(0xffffffffu, v, d);
        if (lane == 0) sm[wid] = v;
        __syncthreads();
        if (wid == 0) {
            float x = sm[lane & 15];
            #pragma unroll
            for (int d = 8; d > 0; d >>= 1) x += __shfl_xor_sync(0xffffffffu, x, d);
            if (lane == 0) sm[0] = x;
        }
        __syncthreads();
        return sm[0];
    };
    auto redmax = [&](float v) -> float {
        __syncthreads();
        #pragma unroll
        for (int d = 16; d > 0; d >>= 1) v = fmaxf(v, __shfl_xor_sync(0xffffffffu, v, d));
        if (lane == 0) sm[wid] = v;
        __syncthreads();
        if (wid == 0) {
            float x = sm[lane & 15];
            #pragma unroll
            for (int d = 8; d > 0; d >>= 1) x = fmaxf(x, __shfl_xor_sync(0xffffffffu, x, d));
            if (lane == 0) sm[0] = x;
        }
        __syncthreads();
        return sm[0];
    };
    auto redargmax = [&](float v, int i) -> int {
        __syncthreads();
        #pragma unroll
        for (int d = 16; d > 0; d >>= 1) {
            float ov = __shfl_xor_sync(0xffffffffu, v, d);
            int   oi = __shfl_xor_sync(0xffffffffu, i, d);
            if (ov > v || (ov == v && oi < i)) { v = ov; i = oi; }
        }
        if (lane == 0) { sm[wid] = v; smi[wid] = i; }
        __syncthreads();
        if (wid == 0) {
            float x = sm[lane & 15]; int xi = smi[lane & 15];
            #pragma unroll
            for (int d = 8; d > 0; d >>= 1) {
                float ov = __shfl_xor_sync(0xffffffffu, x, d);
                int   oi = __shfl_xor_sync(0xffffffffu, xi, d);
                if (ov > x || (ov == x && oi < xi)) { x = ov; xi = oi; }
            }
            if (lane == 0) smi[0] = xi;
        }
        __syncthreads();
        return smi[0];
    };

    float vmax = -1e30f;
    #pragma unroll
    for (int r = 0; r < 8; r++) { lv[r] = g_imp[k][t + r * 512]; vmax = fmaxf(vmax, lv[r]); }
    const float M = redmax(vmax);

    float lsum = 0.f;
    #pragma unroll
    for (int r = 0; r < 8; r++) { lv[r] = expf(lv[r] - M); lsum += lv[r]; }
    const float invS = 1.f / redsum(lsum);

    float tsum = 0.f;
    #pragma unroll
    for (int r = 0; r < 8; r++) { lv[r] *= invS; tsum += lv[r]; }
    const float mean = redsum(tsum) / (float)EE;

    float lvar = 0.f;
    #pragma unroll
    for (int r = 0; r < 8; r++) { float d = lv[r] - mean; lvar += d * d; }
    const float stdv = sqrtf(redsum(lvar) / (float)(EE - 1));

    float ep = epoch_to_float(epochp);
    float theta_c = TC0C + (1.f - expf(-LAMS * ep)) * (TCMAXC - TC0C);
    float theta = fminf(theta_c, mean + stdv);

    float seg = 0.f, pmax = -1e30f; int pam = EE;
    float le[8];
    #pragma unroll
    for (int r = 0; r < 8; r++) {
        int idx = t + r * 512;
        float p = lv[r];
        float e_g = fminf(fmaxf((p - theta) / EPSG + 0.5f, 0.f), 1.f);
        le[r] = e_g; seg += e_g;
        if (p > pmax) { pmax = p; pam = idx; }
    }
    const float sumEg = redsum(seg);
    const int am = redargmax(pmax, pam);

    #pragma unroll
    for (int r = 0; r < 8; r++) {
        int idx = t + r * 512;
        float v = le[r];
        if (sumEg < 1.f && idx == am) v = 1.f;
        g_eg[k][idx] = v;
        out_eg[(size_t)k * EE + idx] = v;
    }
}

// ---------------- 5a: zero-fill Hp for gate==0 components (overlaps k_edge) ----------------
__global__ __launch_bounds__(256) void k_hp0(float* __restrict__ out) {
    int k = blockIdx.y;
    if (g_gates[k] > 0.f) return;
    const float4 z = make_float4(0.f, 0.f, 0.f, 0.f);
    float4* dst = (float4*)(out + (size_t)k * NN * EE) + (size_t)blockIdx.x * 2048 + threadIdx.x;
    #pragma unroll
    for (int r = 0; r < 8; r++) dst[r * 256] = z;
}

// ---------------- 5b: write Hp for gate>0 components ----------------
__global__ __launch_bounds__(256) void k_hp(float* __restrict__ out) {
    int k = blockIdx.z, nt = blockIdx.y, et = blockIdx.x;
    int t = threadIdx.x;
    float g = g_gates[k];
    if (g <= 0.f) return;
    __shared__ ull bw[128];
    __shared__ float hv[128];
    if (t < 128) {
        int e = et * 128 + t;
        float eg = g_eg[k][e];
        hv[t] = g * (g > 0.5f ? eg : 1.f);
        bw[t] = g_colbits[k][e][nt];
    }
    __syncthreads();
    #pragma unroll
    for (int r = 0; r < 8; r++) {
        int idx = t + r * 256;
        int nl = idx >> 5, q = idx & 31, el = q * 4;
        float4 v;
        v.x = ((bw[el + 0] >> nl) & 1ull) ? hv[el + 0] : 0.f;
        v.y = ((bw[el + 1] >> nl) & 1ull) ? hv[el + 1] : 0.f;
        v.z = ((bw[el + 2] >> nl) & 1ull) ? hv[el + 2] : 0.f;
        v.w = ((bw[el + 3] >> nl) & 1ull) ? hv[el + 3] : 0.f;
        *(float4*)&out[((size_t)k * NN + (size_t)nt * 64 + nl) * EE + et * 128 + el] = v;
    }
}

// ---------------- 6: sparse adjacency build (warp per edge) ----------------
__global__ __launch_bounds__(256) void k_adj() {
    int wId = (blockIdx.x * blockDim.x + threadIdx.x) >> 5;
    int lane = threadIdx.x & 31;
    int wl = threadIdx.x >> 5;
    int k = wId / EE, e = wId % EE;
    __shared__ unsigned short list[8][1024];
    __shared__ int scnt[8];
    float g = g_gates[k];
    if (g <= 0.f) return;
    if (g > 0.5f && g_eg[k][e] <= 0.f) return;
    if (g_cnt[k][e] < 2) return;
    if (lane == 0) scnt[wl] = 0;
    __syncwarp();
    ull m = g_colbits[k][e][lane];
    while (m) {
        int b = __ffsll((long long)m) - 1;
        m &= m - 1;
        int pos = atomicAdd(&scnt[wl], 1);
        if (pos < 1024) list[wl][pos] = (unsigned short)(lane * 64 + b);
    }
    __syncwarp();
    int cN = scnt[wl];
    if (cN > 1024) cN = 1024;
    for (int p = lane; p < cN * cN; p += 32) {
        int u = list[wl][p / cN];
        int v = list[wl][p % cN];
        if (u != v)
            atomicOr(&g_adj[k][u][v >> 6], 1ull << (v & 63));
    }
}

// ---------------- 7: neighbor sum -> logits (4 warps, half2 rows, 2x unroll) ----------------
__global__ __launch_bounds__(128) void k_nsum() {
    int u = blockIdx.x, k = blockIdx.y, t = threadIdx.x;
    int w = t >> 5, lane = t & 31;
    __shared__ unsigned short list[NN];
    __shared__ int s_deg;
    __shared__ float wsum[4];
    if (t < 32) {
        ull m = g_adj[k][u][t];
        int c = __popcll(m);
        int off = c;
        #pragma unroll
        for (int d = 1; d < 32; d <<= 1) {
            int x = __shfl_up_sync(0xffffffffu, off, d);
            if (t >= d) off += x;
        }
        off -= c;
        int pos = off;
        while (m) {
            int b = __ffsll((long long)m) - 1;
            m &= m - 1;
            list[pos++] = (unsigned short)(t * 64 + b);
        }
        if (t == 31) s_deg = off + c;
    }
    __syncthreads();
    int deg = s_deg;
    if (deg == 0) {
        if (t == 0) g_logits[k][u] = 0.f;
        return;
    }
    float4 acc = make_float4(0.f, 0.f, 0.f, 0.f);
    float4 acc2 = make_float4(0.f, 0.f, 0.f, 0.f);
    int i = w;
    for (; i + 4 < deg; i += 8) {
        int v0 = list[i], v1 = list[i + 4];
        const __half2* r0 = (const __half2*)&g_xhat_h[v0][lane * 4];
        const __half2* r1 = (const __half2*)&g_xhat_h[v1][lane * 4];
        __half2 a0 = r0[0], b0 = r0[1], a1 = r1[0], b1 = r1[1];
        float2 fa0 = __half22float2(a0), fb0 = __half22float2(b0);
        float2 fa1 = __half22float2(a1), fb1 = __half22float2(b1);
        acc.x += fa0.x; acc.y += fa0.y; acc.z += fb0.x; acc.w += fb0.y;
        acc2.x += fa1.x; acc2.y += fa1.y; acc2.z += fb1.x; acc2.w += fb1.y;
    }
    if (i < deg) {
        const __half2* r0 = (const __half2*)&g_xhat_h[list[i]][lane * 4];
        float2 fa = __half22float2(r0[0]), fb = __half22float2(r0[1]);
        acc.x += fa.x; acc.y += fa.y; acc.z += fb.x; acc.w += fb.y;
    }
    acc.x += acc2.x; acc.y += acc2.y; acc.z += acc2.z; acc.w += acc2.w;
    float4 uf = *(const float4*)&g_xhat[u][lane * 4];
    float d = acc.x * uf.x + acc.y * uf.y + acc.z * uf.z + acc.w * uf.w;
    #pragma unroll
    for (int s = 16; s > 0; s >>= 1) d += __shfl_xor_sync(0xffffffffu, d, s);
    if (lane == 0) wsum[w] = d;
    __syncthreads();
    if (t == 0) {
        float tot = (wsum[0] + wsum[1]) + (wsum[2] + wsum[3]);
        g_logits[k][u] = (tot / (float)deg) * g_xnorm[u];
    }
}

// ---------------- 8: npi softmax over nodes ----------------
__global__ __launch_bounds__(512) void k_npi(float* __restrict__ out_npi) {
    int k = blockIdx.x, t = threadIdx.x;
    __shared__ float red[512];
    float lv[4];
    float m = -1e30f;
    #pragma unroll
    for (int r = 0; r < 4; r++) { lv[r] = g_logits[k][t + r * 512]; m = fmaxf(m, lv[r]); }
    red[t] = m; __syncthreads();
    for (int s = 256; s > 0; s >>= 1) { if (t < s) red[t] = fmaxf(red[t], red[t + s]); __syncthreads(); }
    const float M = red[0]; __syncthreads();
    float ls = 0.f;
    #pragma unroll
    for (int r = 0; r < 4; r++) { lv[r] = expf(lv[r] - M); ls += lv[r]; }
    red[t] = ls; __syncthreads();
    for (int s = 256; s > 0; s >>= 1) { if (t < s) red[t] += red[t + s]; __syncthreads(); }
    const float invS = 1.f / red[0];
    #pragma unroll
    for (int r = 0; r < 4; r++)
        out_npi[(size_t)k * NN + t + r * 512] = lv[r] * invS;
}

// ---------------- launch (3-stream fork/join graph) ----------------
static cudaStream_t g_s2 = nullptr, g_s3 = nullptr;
static cudaEvent_t g_eI = nullptr, g_eG = nullptr, g_eEG = nullptr,
                   g_ePA = nullptr, g_eT = nullptr;
static int g_multi = -1;

extern "C" void kernel_launch(void* const* d_in, const int* in_sizes, int n_in,
                              void* d_out, int out_size) {
    const float* H     = (const float*)d_in[0];
    const float* X     = (const float*)d_in[1];
    const int*   epoch = (const int*)  d_in[2];
    const float* w1    = (const float*)d_in[3];
    const float* b1    = (const float*)d_in[4];
    const float* w2    = (const float*)d_in[5];
    const float* b2    = (const float*)d_in[6];
    const float* compW = (const float*)d_in[7];
    const float* aw1   = (const float*)d_in[8];
    const float* ab1   = (const float*)d_in[9];
    const float* aw2   = (const float*)d_in[10];
    const float* ab2   = (const float*)d_in[11];
    float* out = (float*)d_out;

    const size_t OFF_G = (size_t)KK * NN * EE;
    const size_t OFF_E = OFF_G + KK;
    const size_t OFF_P = OFF_E + (size_t)KK * EE;

    cudaFuncSetAttribute(k_gemm, cudaFuncAttributeMaxDynamicSharedMemorySize, SM_BYTES);

    if (g_multi < 0) {
        bool ok = (cudaStreamCreateWithFlags(&g_s2, cudaStreamNonBlocking) == cudaSuccess)
               && (cudaStreamCreateWithFlags(&g_s3, cudaStreamNonBlocking) == cudaSuccess)
               && (cudaEventCreateWithFlags(&g_eI, cudaEventDisableTiming) == cudaSuccess)
               && (cudaEventCreateWithFlags(&g_eG, cudaEventDisableTiming) == cudaSuccess)
               && (cudaEventCreateWithFlags(&g_eEG, cudaEventDisableTiming) == cudaSuccess)
               && (cudaEventCreateWithFlags(&g_ePA, cudaEventDisableTiming) == cudaSuccess)
               && (cudaEventCreateWithFlags(&g_eT, cudaEventDisableTiming) == cudaSuccess);
        g_multi = ok ? 1 : 0;
    }

    if (g_multi == 1) {
        // s0: init -> edge -> eg -> (wait gates) hp -> (join)
        k_init<<<NN, 128>>>(X, compW);
        cudaEventRecord(g_eI, 0);
        // s2: gemm -> gates -> hp0 (zero-fill overlaps edge)
        cudaStreamWaitEvent(g_s2, g_eI, 0);
        k_gemm<<<dim3(NN / GM, KK), 128, SM_BYTES, g_s2>>>(X, w1, b1, w2, b2, aw1, ab1, aw2, ab2);
        k_gates<<<1, 64, 0, g_s2>>>(epoch, out + OFF_G);
        cudaEventRecord(g_eG, g_s2);
        k_hp0<<<dim3(1024, KK), 256, 0, g_s2>>>(out);
        cudaEventRecord(g_ePA, g_s2);
        // s0: edge (starts right after init), then eg
        k_edge<<<dim3(EE / 32, KK), 256>>>(H);
        k_eg<<<KK, 512>>>(epoch, out + OFF_E);
        cudaEventRecord(g_eEG, 0);
        // s3: adj -> nsum -> npi (needs gates + eg)
        cudaStreamWaitEvent(g_s3, g_eG, 0);
        cudaStreamWaitEvent(g_s3, g_eEG, 0);
        k_adj<<<KK * EE / 8, 256, 0, g_s3>>>();
        k_nsum<<<dim3(NN, KK), 128, 0, g_s3>>>();
        k_npi<<<KK, 512, 0, g_s3>>>(out + OFF_P);
        cudaEventRecord(g_eT, g_s3);
        // s0: hp (gate>0 components; needs gates + eg)
        cudaStreamWaitEvent(0, g_eG, 0);
        k_hp<<<dim3(EE / 128, NN / 64, KK), 256>>>(out);
        // join
        cudaStreamWaitEvent(0, g_ePA, 0);
        cudaStreamWaitEvent(0, g_eT, 0);
    } else {
        k_init<<<NN, 128>>>(X, compW);
        k_edge<<<dim3(EE / 32, KK), 256>>>(H);
        k_gemm<<<dim3(NN / GM, KK), 128, SM_BYTES>>>(X, w1, b1, w2, b2, aw1, ab1, aw2, ab2);
        k_gates<<<1, 64>>>(epoch, out + OFF_G);
        k_eg<<<KK, 512>>>(epoch, out + OFF_E);
        k_hp0<<<dim3(1024, KK), 256>>>(out);
        k_hp<<<dim3(EE / 128, NN / 64, KK), 256>>>(out);
        k_adj<<<KK * EE / 8, 256>>>();
        k_nsum<<<dim3(NN, KK), 128>>>();
        k_npi<<<KK, 512>>>(out + OFF_P);
    }
}